// round 1
// baseline (speedup 1.0000x reference)
#include <cuda_runtime.h>
#include <math.h>

#define BATCH   2
#define NSEQ    2048
#define DMODEL  512
#define NHEADS  8
#define DH      64
#define KP      32
#define TAU_F   6.283185307179586f

// ---------------- scratch (static device memory; no allocations) ----------------
__device__ float g_qkv[(size_t)BATCH * NSEQ * 3 * DMODEL];          // (b,n,3,h,dh)
__device__ float g_q[(size_t)BATCH * NHEADS * NSEQ * DH];           // (b,h,n,dh) rotated
__device__ float g_k[(size_t)BATCH * NHEADS * NSEQ * DH];           // (b,h,n,dh) rotated
__device__ float g_v[(size_t)BATCH * NHEADS * NSEQ * DH];           // (b,h,n,dh)
__device__ float g_cos[NHEADS * NSEQ * KP];
__device__ float g_sin[NHEADS * NSEQ * KP];
__device__ float g_sheet[NHEADS * NSEQ * KP];
__device__ float g_att[(size_t)BATCH * NSEQ * DMODEL];              // (b,n,h*dh)

__constant__ float c_zim[KP] = {
    14.134725142f, 21.022039639f, 25.01085758f,  30.424876126f,
    32.935061588f, 37.586178159f, 40.918719012f, 43.327073281f,
    48.005150881f, 49.773832478f, 52.970321478f, 56.446247697f,
    59.347044003f, 60.831778525f, 65.112544048f, 67.079810529f,
    69.546401711f, 72.067157674f, 75.704690699f, 77.144840069f,
    79.33737502f,  82.910380854f, 84.735492981f, 87.425274613f,
    88.809111208f, 92.491899271f, 94.651344041f, 95.870634228f,
    98.831194218f, 101.317851006f, 103.72553804f, 105.446623052f};

// ---------------- SGEMM: C[M,N] = A[M,K] @ B[K,N], row-major, 128x128x16 tile ----------------
__global__ __launch_bounds__(256) void sgemm128(const float* __restrict__ A,
                                                const float* __restrict__ B,
                                                float* __restrict__ C,
                                                int M, int N, int K) {
    __shared__ __align__(16) float As[16][128];   // As[k][m]
    __shared__ __align__(16) float Bs[16][128];   // Bs[k][n]

    const int tid = threadIdx.x;
    const int tx = tid & 15;       // 0..15 -> 8 cols each
    const int ty = tid >> 4;       // 0..15 -> 8 rows each
    const int row0 = blockIdx.y * 128;
    const int col0 = blockIdx.x * 128;

    float acc[8][8];
#pragma unroll
    for (int i = 0; i < 8; i++)
#pragma unroll
        for (int j = 0; j < 8; j++) acc[i][j] = 0.0f;

    for (int k0 = 0; k0 < K; k0 += 16) {
        // load A tile 128x16 (as float4 along K), store transposed
        for (int i = tid; i < 512; i += 256) {
            int m = i >> 2, kq = i & 3;
            float4 a = *reinterpret_cast<const float4*>(
                &A[(size_t)(row0 + m) * K + k0 + kq * 4]);
            As[kq * 4 + 0][m] = a.x;
            As[kq * 4 + 1][m] = a.y;
            As[kq * 4 + 2][m] = a.z;
            As[kq * 4 + 3][m] = a.w;
        }
        // load B tile 16x128 (float4 along N)
        for (int i = tid; i < 512; i += 256) {
            int kk = i >> 5, nq = i & 31;
            *reinterpret_cast<float4*>(&Bs[kk][nq * 4]) =
                *reinterpret_cast<const float4*>(
                    &B[(size_t)(k0 + kk) * N + col0 + nq * 4]);
        }
        __syncthreads();
#pragma unroll
        for (int kk = 0; kk < 16; kk++) {
            float a[8], b[8];
            float4 a0 = *reinterpret_cast<const float4*>(&As[kk][ty * 8]);
            float4 a1 = *reinterpret_cast<const float4*>(&As[kk][ty * 8 + 4]);
            float4 b0 = *reinterpret_cast<const float4*>(&Bs[kk][tx * 8]);
            float4 b1 = *reinterpret_cast<const float4*>(&Bs[kk][tx * 8 + 4]);
            a[0] = a0.x; a[1] = a0.y; a[2] = a0.z; a[3] = a0.w;
            a[4] = a1.x; a[5] = a1.y; a[6] = a1.z; a[7] = a1.w;
            b[0] = b0.x; b[1] = b0.y; b[2] = b0.z; b[3] = b0.w;
            b[4] = b1.x; b[5] = b1.y; b[6] = b1.z; b[7] = b1.w;
#pragma unroll
            for (int i = 0; i < 8; i++)
#pragma unroll
                for (int j = 0; j < 8; j++) acc[i][j] += a[i] * b[j];
        }
        __syncthreads();
    }
#pragma unroll
    for (int i = 0; i < 8; i++) {
        size_t off = (size_t)(row0 + ty * 8 + i) * N + col0 + tx * 8;
        float4 c0 = make_float4(acc[i][0], acc[i][1], acc[i][2], acc[i][3]);
        float4 c1 = make_float4(acc[i][4], acc[i][5], acc[i][6], acc[i][7]);
        *reinterpret_cast<float4*>(&C[off]) = c0;
        *reinterpret_cast<float4*>(&C[off + 4]) = c1;
    }
}

// ---------------- theta / cos / sin / sheet ----------------
__global__ void prep_kernel(const float* __restrict__ log_scale) {
    int idx = blockIdx.x * blockDim.x + threadIdx.x;   // h*NSEQ + n
    if (idx >= NHEADS * NSEQ) return;
    int h = idx / NSEQ;
    int n = idx % NSEQ;
    float sc = expf(log_scale[h]);
    float tau = log1pf((float)n);
#pragma unroll
    for (int p = 0; p < KP; p++) {
        float g = c_zim[p] / c_zim[0];
        float th = tau * g * sc;
        g_cos[idx * KP + p] = cosf(th);
        g_sin[idx * KP + p] = sinf(th);
        g_sheet[idx * KP + p] = floorf(th / TAU_F);
    }
}

// ---------------- rotate q,k pairs + transpose to (b,h,n,dh); copy v ----------------
__global__ void rotate_kernel() {
    int idx = blockIdx.x * blockDim.x + threadIdx.x;   // over B*H*N*KP
    if (idx >= BATCH * NHEADS * NSEQ * KP) return;
    int p = idx & (KP - 1);
    int t = idx >> 5;               // /KP
    int n = t % NSEQ; t /= NSEQ;
    int h = t % NHEADS;
    int b = t / NHEADS;

    int hp = h * NSEQ + n;
    float c = g_cos[hp * KP + p];
    float s = g_sin[hp * KP + p];

    size_t base = ((size_t)(b * NSEQ + n) * 3) * DMODEL;   // + w*512 + h*64 + d
    int d0 = 2 * p;
    float q1 = g_qkv[base + 0 * DMODEL + h * DH + d0];
    float q2 = g_qkv[base + 0 * DMODEL + h * DH + d0 + 1];
    float k1 = g_qkv[base + 1 * DMODEL + h * DH + d0];
    float k2 = g_qkv[base + 1 * DMODEL + h * DH + d0 + 1];
    float v1 = g_qkv[base + 2 * DMODEL + h * DH + d0];
    float v2 = g_qkv[base + 2 * DMODEL + h * DH + d0 + 1];

    size_t ob = ((size_t)((b * NHEADS + h) * NSEQ) + n) * DH + d0;
    g_q[ob]     = q1 * c - q2 * s;
    g_q[ob + 1] = q1 * s + q2 * c;
    g_k[ob]     = k1 * c - k2 * s;
    g_k[ob + 1] = k1 * s + k2 * c;
    g_v[ob]     = v1;
    g_v[ob + 1] = v2;
}

// ---------------- fused causal attention with sheet-bias ----------------
// grid: (B*H, NSEQ/8), 256 threads = 8 warps, 1 query row per warp.
__global__ __launch_bounds__(256) void attn_kernel(const float* __restrict__ log_lambda_sigma) {
    __shared__ __align__(16) float q_s[8][DH];      // query rows
    __shared__ __align__(16) float sq_s[8][KP];     // query sheet rows
    __shared__ __align__(16) float ksT[DH][66];     // K tile transposed [d][j], pad for banks
    __shared__ __align__(16) float sk_s[KP][66];    // key sheet transposed [p][j]
    __shared__ __align__(16) float vs[64][DH];      // V tile [j][d]
    __shared__ __align__(16) float p_s[8][64];      // probs per warp-row

    const int bh = blockIdx.x;
    const int h = bh % NHEADS;
    const int b = bh / NHEADS;
    const int qbase = blockIdx.y * 8;
    const int warp = threadIdx.x >> 5;
    const int lane = threadIdx.x & 31;
    const int row = qbase + warp;

    const float lam = expf(log_lambda_sigma[h]);
    const float* qptr = g_q + (size_t)bh * NSEQ * DH;
    const float* kptr = g_k + (size_t)bh * NSEQ * DH;
    const float* vptr = g_v + (size_t)bh * NSEQ * DH;
    const float* shp  = g_sheet + (size_t)h * NSEQ * KP;

    // load query rows + query sheets
    for (int i = threadIdx.x; i < 8 * DH; i += 256) {
        int r = i >> 6, d = i & 63;
        q_s[r][d] = qptr[(size_t)(qbase + r) * DH + d];
    }
    for (int i = threadIdx.x; i < 8 * KP; i += 256) {
        int r = i >> 5, p = i & 31;
        sq_s[r][p] = shp[(size_t)(qbase + r) * KP + p];
    }

    float m = -INFINITY, l = 0.0f, o0 = 0.0f, o1 = 0.0f;
    const int ntiles = qbase / 64 + 1;   // uniform across the block (qbase%64 <= 56)
    const int j0 = 2 * lane, j1 = 2 * lane + 1;

    for (int t = 0; t < ntiles; t++) {
        const int jg = t * 64;
        __syncthreads();   // protect previous tile's smem + initial q loads
        // K transposed, V, key-sheet transposed
        for (int i = threadIdx.x; i < 64 * DH; i += 256) {
            int j = i >> 6, d = i & 63;
            ksT[d][j] = kptr[(size_t)(jg + j) * DH + d];
            vs[j][d]  = vptr[(size_t)(jg + j) * DH + d];
        }
        for (int i = threadIdx.x; i < 64 * KP; i += 256) {
            int j = i >> 5, p = i & 31;
            sk_s[p][j] = shp[(size_t)(jg + j) * KP + p];
        }
        __syncthreads();

        // scores for this warp's row: lane handles keys jg+j0, jg+j1
        float s0 = -INFINITY, s1 = -INFINITY;
        if (jg + j0 <= row) {
            float acc = 0.0f, sb = 0.0f;
#pragma unroll
            for (int d = 0; d < DH; d++) {
                float2 k2 = *reinterpret_cast<const float2*>(&ksT[d][j0]);
                acc += q_s[warp][d] * k2.x;
            }
#pragma unroll
            for (int p = 0; p < KP; p++) {
                float2 s2 = *reinterpret_cast<const float2*>(&sk_s[p][j0]);
                sb += fabsf(sq_s[warp][p] - s2.x);
            }
            s0 = acc * 0.125f - lam * sb * (1.0f / KP);
        }
        if (jg + j1 <= row) {
            float acc = 0.0f, sb = 0.0f;
#pragma unroll
            for (int d = 0; d < DH; d++) {
                float2 k2 = *reinterpret_cast<const float2*>(&ksT[d][j0]);
                acc += q_s[warp][d] * k2.y;
            }
#pragma unroll
            for (int p = 0; p < KP; p++) {
                float2 s2 = *reinterpret_cast<const float2*>(&sk_s[p][j0]);
                sb += fabsf(sq_s[warp][p] - s2.y);
            }
            s1 = acc * 0.125f - lam * sb * (1.0f / KP);
        }

        // online softmax (warp-wide)
        float tm = fmaxf(s0, s1);
#pragma unroll
        for (int off = 16; off; off >>= 1)
            tm = fmaxf(tm, __shfl_xor_sync(0xffffffffu, tm, off));
        float mnew = fmaxf(m, tm);
        float corr = expf(m - mnew);                 // 0 on first tile (m=-inf)
        float p0 = expf(s0 - mnew);                  // exp(-inf)=0 for masked
        float p1 = expf(s1 - mnew);
        float ls = p0 + p1;
#pragma unroll
        for (int off = 16; off; off >>= 1)
            ls += __shfl_xor_sync(0xffffffffu, ls, off);
        l = l * corr + ls;
        o0 *= corr;
        o1 *= corr;
        m = mnew;

        p_s[warp][j0] = p0;
        p_s[warp][j1] = p1;
        __syncwarp();

        // PV: lane accumulates output dims 2*lane, 2*lane+1
        const int d0 = 2 * lane;
#pragma unroll
        for (int j = 0; j < 64; j++) {
            float pj = p_s[warp][j];
            float2 v2 = *reinterpret_cast<const float2*>(&vs[j][d0]);
            o0 += pj * v2.x;
            o1 += pj * v2.y;
        }
    }

    float inv = 1.0f / l;
    size_t ob = ((size_t)(b * NSEQ + row)) * DMODEL + h * DH + 2 * lane;
    g_att[ob]     = o0 * inv;
    g_att[ob + 1] = o1 * inv;
}

// ---------------- launch ----------------
extern "C" void kernel_launch(void* const* d_in, const int* in_sizes, int n_in,
                              void* d_out, int out_size) {
    const float* x      = (const float*)d_in[0];   // (2,2048,512)
    const float* w_qkv  = (const float*)d_in[1];   // (512,1536)
    const float* w_o    = (const float*)d_in[2];   // (512,512)
    const float* lscale = (const float*)d_in[3];   // (8,)
    const float* lls    = (const float*)d_in[4];   // (8,)
    float* out = (float*)d_out;

    float *qkv, *att;
    cudaGetSymbolAddress((void**)&qkv, g_qkv);
    cudaGetSymbolAddress((void**)&att, g_att);

    const int M = BATCH * NSEQ;   // 4096

    // 1) QKV projection: (4096,512)@(512,1536)
    sgemm128<<<dim3((3 * DMODEL) / 128, M / 128), 256>>>(x, w_qkv, qkv, M, 3 * DMODEL, DMODEL);

    // 2) theta/cos/sin/sheet
    prep_kernel<<<(NHEADS * NSEQ + 127) / 128, 128>>>(lscale);

    // 3) rotate + transpose heads
    rotate_kernel<<<(BATCH * NHEADS * NSEQ * KP) / 256, 256>>>();

    // 4) fused causal attention with sheet-bias
    attn_kernel<<<dim3(BATCH * NHEADS, NSEQ / 8), 256>>>(lls);

    // 5) output projection: (4096,512)@(512,512)
    sgemm128<<<dim3(DMODEL / 128, M / 128), 256>>>(att, w_o, out, M, DMODEL, DMODEL);
}

// round 2
// speedup vs baseline: 2.9508x; 2.9508x over previous
#include <cuda_runtime.h>
#include <math.h>

#define BATCH   2
#define NSEQ    2048
#define DMODEL  512
#define NHEADS  8
#define DH      64
#define KP      32
#define TAU_F   6.283185307179586f

// ---------------- scratch (static device memory; no allocations) ----------------
__device__ float g_qkv[(size_t)BATCH * NSEQ * 3 * DMODEL];          // (b,n,3,h,dh)
__device__ float g_q[(size_t)BATCH * NHEADS * NSEQ * DH];           // (b,h,n,dh) rotated
__device__ float g_k[(size_t)BATCH * NHEADS * NSEQ * DH];           // (b,h,n,dh) rotated
__device__ float g_v[(size_t)BATCH * NHEADS * NSEQ * DH];           // (b,h,n,dh)
__device__ float g_cos[NHEADS * NSEQ * KP];
__device__ float g_sin[NHEADS * NSEQ * KP];
__device__ float g_bias[NHEADS * NSEQ];                             // lam*S_n/KP per head
__device__ float g_att[(size_t)BATCH * NSEQ * DMODEL];              // (b,n,h*dh)

__constant__ float c_zim[KP] = {
    14.134725142f, 21.022039639f, 25.01085758f,  30.424876126f,
    32.935061588f, 37.586178159f, 40.918719012f, 43.327073281f,
    48.005150881f, 49.773832478f, 52.970321478f, 56.446247697f,
    59.347044003f, 60.831778525f, 65.112544048f, 67.079810529f,
    69.546401711f, 72.067157674f, 75.704690699f, 77.144840069f,
    79.33737502f,  82.910380854f, 84.735492981f, 87.425274613f,
    88.809111208f, 92.491899271f, 94.651344041f, 95.870634228f,
    98.831194218f, 101.317851006f, 103.72553804f, 105.446623052f};

// ---------------- SGEMM: C[M,N] = A[M,K] @ B[K,N], row-major, 128x128x16 tile ----------------
__global__ __launch_bounds__(256) void sgemm128(const float* __restrict__ A,
                                                const float* __restrict__ B,
                                                float* __restrict__ C,
                                                int M, int N, int K) {
    __shared__ __align__(16) float As[16][128];
    __shared__ __align__(16) float Bs[16][128];

    const int tid = threadIdx.x;
    const int tx = tid & 15;
    const int ty = tid >> 4;
    const int row0 = blockIdx.y * 128;
    const int col0 = blockIdx.x * 128;

    float acc[8][8];
#pragma unroll
    for (int i = 0; i < 8; i++)
#pragma unroll
        for (int j = 0; j < 8; j++) acc[i][j] = 0.0f;

    for (int k0 = 0; k0 < K; k0 += 16) {
        for (int i = tid; i < 512; i += 256) {
            int m = i >> 2, kq = i & 3;
            float4 a = *reinterpret_cast<const float4*>(
                &A[(size_t)(row0 + m) * K + k0 + kq * 4]);
            As[kq * 4 + 0][m] = a.x;
            As[kq * 4 + 1][m] = a.y;
            As[kq * 4 + 2][m] = a.z;
            As[kq * 4 + 3][m] = a.w;
        }
        for (int i = tid; i < 512; i += 256) {
            int kk = i >> 5, nq = i & 31;
            *reinterpret_cast<float4*>(&Bs[kk][nq * 4]) =
                *reinterpret_cast<const float4*>(
                    &B[(size_t)(k0 + kk) * N + col0 + nq * 4]);
        }
        __syncthreads();
#pragma unroll
        for (int kk = 0; kk < 16; kk++) {
            float a[8], b[8];
            float4 a0 = *reinterpret_cast<const float4*>(&As[kk][ty * 8]);
            float4 a1 = *reinterpret_cast<const float4*>(&As[kk][ty * 8 + 4]);
            float4 b0 = *reinterpret_cast<const float4*>(&Bs[kk][tx * 8]);
            float4 b1 = *reinterpret_cast<const float4*>(&Bs[kk][tx * 8 + 4]);
            a[0] = a0.x; a[1] = a0.y; a[2] = a0.z; a[3] = a0.w;
            a[4] = a1.x; a[5] = a1.y; a[6] = a1.z; a[7] = a1.w;
            b[0] = b0.x; b[1] = b0.y; b[2] = b0.z; b[3] = b0.w;
            b[4] = b1.x; b[5] = b1.y; b[6] = b1.z; b[7] = b1.w;
#pragma unroll
            for (int i = 0; i < 8; i++)
#pragma unroll
                for (int j = 0; j < 8; j++) acc[i][j] += a[i] * b[j];
        }
        __syncthreads();
    }
#pragma unroll
    for (int i = 0; i < 8; i++) {
        size_t off = (size_t)(row0 + ty * 8 + i) * N + col0 + tx * 8;
        *reinterpret_cast<float4*>(&C[off]) =
            make_float4(acc[i][0], acc[i][1], acc[i][2], acc[i][3]);
        *reinterpret_cast<float4*>(&C[off + 4]) =
            make_float4(acc[i][4], acc[i][5], acc[i][6], acc[i][7]);
    }
}

// ---------------- theta / cos / sin / per-key bias ----------------
// Since theta(n) is strictly increasing in n for every (h,p), sheet_p(n) is
// monotone, so mean_p|sheet_i-sheet_j| = (S_i - S_j)/KP for j<=i. The -S_i term
// is a per-row softmax constant (cancels); only +lam*S_j/KP per KEY survives.
__global__ void prep_kernel(const float* __restrict__ log_scale,
                            const float* __restrict__ log_lambda_sigma) {
    int idx = blockIdx.x * blockDim.x + threadIdx.x;   // h*NSEQ + n
    if (idx >= NHEADS * NSEQ) return;
    int h = idx / NSEQ;
    int n = idx % NSEQ;
    float sc = expf(log_scale[h]);
    float lam = expf(log_lambda_sigma[h]);
    float tau = log1pf((float)n);
    float ssum = 0.0f;
#pragma unroll
    for (int p = 0; p < KP; p++) {
        float g = c_zim[p] / c_zim[0];
        float th = tau * g * sc;
        g_cos[idx * KP + p] = cosf(th);
        g_sin[idx * KP + p] = sinf(th);
        ssum += floorf(th / TAU_F);
    }
    g_bias[idx] = lam * ssum * (1.0f / KP);
}

// ---------------- rotate q,k pairs + transpose to (b,h,n,dh); copy v ----------------
__global__ void rotate_kernel() {
    int idx = blockIdx.x * blockDim.x + threadIdx.x;   // over B*H*N*KP
    if (idx >= BATCH * NHEADS * NSEQ * KP) return;
    int p = idx & (KP - 1);
    int t = idx >> 5;
    int n = t % NSEQ; t /= NSEQ;
    int h = t % NHEADS;
    int b = t / NHEADS;

    int hp = h * NSEQ + n;
    float c = g_cos[hp * KP + p];
    float s = g_sin[hp * KP + p];

    size_t base = ((size_t)(b * NSEQ + n) * 3) * DMODEL;
    int d0 = 2 * p;
    float q1 = g_qkv[base + 0 * DMODEL + h * DH + d0];
    float q2 = g_qkv[base + 0 * DMODEL + h * DH + d0 + 1];
    float k1 = g_qkv[base + 1 * DMODEL + h * DH + d0];
    float k2 = g_qkv[base + 1 * DMODEL + h * DH + d0 + 1];
    float v1 = g_qkv[base + 2 * DMODEL + h * DH + d0];
    float v2 = g_qkv[base + 2 * DMODEL + h * DH + d0 + 1];

    size_t ob = ((size_t)((b * NHEADS + h) * NSEQ) + n) * DH + d0;
    g_q[ob]     = q1 * c - q2 * s;
    g_q[ob + 1] = q1 * s + q2 * c;
    g_k[ob]     = k1 * c - k2 * s;
    g_k[ob + 1] = k1 * s + k2 * c;
    g_v[ob]     = v1;
    g_v[ob + 1] = v2;
}

// ---------------- fused causal flash attention, register-tiled ----------------
// Block = 256 threads, handles 64 query rows of one (b,h); key tiles of 64.
// Thread (ty,tx) owns rows 4ty..4ty+3, score-cols/out-dims 4tx..4tx+3.
#define PSTR 68
__global__ __launch_bounds__(256, 2) void attn2_kernel() {
    extern __shared__ float sm[];
    float* qT = sm;                  // [64][68]  qT[d][r]
    float* kT = sm + 64 * PSTR;      // [64][68]  kT[d][j]
    float* vs = sm + 128 * PSTR;     // [64][68]  vs[j][d]
    float* ps = sm + 192 * PSTR;     // [64][68]  ps[r][j]
    float* bs = sm + 256 * PSTR;     // [64]

    const int tid = threadIdx.x;
    const int tx = tid & 15;
    const int ty = tid >> 4;
    const int bh = blockIdx.x;
    const int h = bh & (NHEADS - 1);
    const int b = bh >> 3;
    const int qbase = (int)(gridDim.y - 1 - blockIdx.y) << 6;  // biggest blocks first

    const float* qp = g_q + (size_t)bh * NSEQ * DH;
    const float* kp = g_k + (size_t)bh * NSEQ * DH;
    const float* vp = g_v + (size_t)bh * NSEQ * DH;
    const float* bp = g_bias + h * NSEQ;

    // load Q tile transposed: qT[d][r]
    for (int idx = tid; idx < 1024; idx += 256) {
        int dq = idx >> 6, j = idx & 63;
        float4 a = *reinterpret_cast<const float4*>(
            &qp[(size_t)(qbase + j) * DH + 4 * dq]);
        qT[(4 * dq + 0) * PSTR + j] = a.x;
        qT[(4 * dq + 1) * PSTR + j] = a.y;
        qT[(4 * dq + 2) * PSTR + j] = a.z;
        qT[(4 * dq + 3) * PSTR + j] = a.w;
    }

    float m[4], l[4], o[4][4];
#pragma unroll
    for (int i = 0; i < 4; i++) {
        m[i] = -INFINITY; l[i] = 0.0f;
#pragma unroll
        for (int j = 0; j < 4; j++) o[i][j] = 0.0f;
    }

    const int ntiles = (qbase >> 6) + 1;
    for (int t = 0; t < ntiles; t++) {
        const int jg = t << 6;
        __syncthreads();   // protect prev tile's vs/kT reads + initial qT
        // K transposed, V natural, bias
        for (int idx = tid; idx < 1024; idx += 256) {
            int dq = idx >> 6, j = idx & 63;
            float4 a = *reinterpret_cast<const float4*>(
                &kp[(size_t)(jg + j) * DH + 4 * dq]);
            kT[(4 * dq + 0) * PSTR + j] = a.x;
            kT[(4 * dq + 1) * PSTR + j] = a.y;
            kT[(4 * dq + 2) * PSTR + j] = a.z;
            kT[(4 * dq + 3) * PSTR + j] = a.w;
        }
        for (int idx = tid; idx < 1024; idx += 256) {
            int j = idx >> 4, dq = idx & 15;
            *reinterpret_cast<float4*>(&vs[j * PSTR + 4 * dq]) =
                *reinterpret_cast<const float4*>(
                    &vp[(size_t)(jg + j) * DH + 4 * dq]);
        }
        if (tid < 64) bs[tid] = bp[jg + tid];
        __syncthreads();

        // S = Q K^T (4x4 register tile)
        float s[4][4];
#pragma unroll
        for (int i = 0; i < 4; i++)
#pragma unroll
            for (int j = 0; j < 4; j++) s[i][j] = 0.0f;
#pragma unroll
        for (int d = 0; d < DH; d++) {
            float4 qa = *reinterpret_cast<const float4*>(&qT[d * PSTR + 4 * ty]);
            float4 kb = *reinterpret_cast<const float4*>(&kT[d * PSTR + 4 * tx]);
            float a[4] = {qa.x, qa.y, qa.z, qa.w};
            float bb[4] = {kb.x, kb.y, kb.z, kb.w};
#pragma unroll
            for (int i = 0; i < 4; i++)
#pragma unroll
                for (int j = 0; j < 4; j++) s[i][j] += a[i] * bb[j];
        }

        // scale + per-key bias + causal mask (only diagonal tile needs mask)
        float bj[4] = {bs[4 * tx], bs[4 * tx + 1], bs[4 * tx + 2], bs[4 * tx + 3]};
        const bool diag = (jg == qbase);
#pragma unroll
        for (int i = 0; i < 4; i++)
#pragma unroll
            for (int j = 0; j < 4; j++) {
                float val = s[i][j] * 0.125f + bj[j];
                if (diag && (4 * tx + j > 4 * ty + i)) val = -INFINITY;
                s[i][j] = val;
            }

        // online softmax per row (rows spread over 16 lanes in tx)
#pragma unroll
        for (int i = 0; i < 4; i++) {
            float mi = fmaxf(fmaxf(s[i][0], s[i][1]), fmaxf(s[i][2], s[i][3]));
#pragma unroll
            for (int off = 8; off; off >>= 1)
                mi = fmaxf(mi, __shfl_xor_sync(0xffffffffu, mi, off));
            float mn = fmaxf(m[i], mi);
            float corr = __expf(m[i] - mn);
            m[i] = mn;
            float p0 = __expf(s[i][0] - mn);
            float p1 = __expf(s[i][1] - mn);
            float p2 = __expf(s[i][2] - mn);
            float p3 = __expf(s[i][3] - mn);
            float ls = p0 + p1 + p2 + p3;
#pragma unroll
            for (int off = 8; off; off >>= 1)
                ls += __shfl_xor_sync(0xffffffffu, ls, off);
            l[i] = l[i] * corr + ls;
            o[i][0] *= corr; o[i][1] *= corr; o[i][2] *= corr; o[i][3] *= corr;
            *reinterpret_cast<float4*>(&ps[(4 * ty + i) * PSTR + 4 * tx]) =
                make_float4(p0, p1, p2, p3);
        }
        __syncwarp();   // ps produced/consumed within the same 16-lane ty-group

        // O += P V  (4x4 register tile)
#pragma unroll
        for (int kb4 = 0; kb4 < 16; kb4++) {
            float4 p4[4], vv[4];
#pragma unroll
            for (int i = 0; i < 4; i++)
                p4[i] = *reinterpret_cast<const float4*>(
                    &ps[(4 * ty + i) * PSTR + 4 * kb4]);
#pragma unroll
            for (int c = 0; c < 4; c++)
                vv[c] = *reinterpret_cast<const float4*>(
                    &vs[(4 * kb4 + c) * PSTR + 4 * tx]);
#pragma unroll
            for (int i = 0; i < 4; i++) {
                float pc[4] = {p4[i].x, p4[i].y, p4[i].z, p4[i].w};
#pragma unroll
                for (int c = 0; c < 4; c++) {
                    o[i][0] += pc[c] * vv[c].x;
                    o[i][1] += pc[c] * vv[c].y;
                    o[i][2] += pc[c] * vv[c].z;
                    o[i][3] += pc[c] * vv[c].w;
                }
            }
        }
    }

    // normalize + write (b, n, h*dh)
#pragma unroll
    for (int i = 0; i < 4; i++) {
        float inv = 1.0f / l[i];
        size_t ob = ((size_t)(b * NSEQ + qbase + 4 * ty + i)) * DMODEL + h * DH + 4 * tx;
        *reinterpret_cast<float4*>(&g_att[ob]) =
            make_float4(o[i][0] * inv, o[i][1] * inv, o[i][2] * inv, o[i][3] * inv);
    }
}

// ---------------- launch ----------------
extern "C" void kernel_launch(void* const* d_in, const int* in_sizes, int n_in,
                              void* d_out, int out_size) {
    const float* x      = (const float*)d_in[0];
    const float* w_qkv  = (const float*)d_in[1];
    const float* w_o    = (const float*)d_in[2];
    const float* lscale = (const float*)d_in[3];
    const float* lls    = (const float*)d_in[4];
    float* out = (float*)d_out;

    float *qkv, *att;
    cudaGetSymbolAddress((void**)&qkv, g_qkv);
    cudaGetSymbolAddress((void**)&att, g_att);

    const int M = BATCH * NSEQ;   // 4096
    const int ATTN_SMEM = (256 * PSTR + 64) * (int)sizeof(float);   // ~69.9 KB
    cudaFuncSetAttribute(attn2_kernel,
                         cudaFuncAttributeMaxDynamicSharedMemorySize, ATTN_SMEM);

    // 1) QKV projection
    sgemm128<<<dim3((3 * DMODEL) / 128, M / 128), 256>>>(x, w_qkv, qkv, M, 3 * DMODEL, DMODEL);

    // 2) theta/cos/sin + per-key bias
    prep_kernel<<<(NHEADS * NSEQ + 127) / 128, 128>>>(lscale, lls);

    // 3) rotate + transpose heads
    rotate_kernel<<<(BATCH * NHEADS * NSEQ * KP) / 256, 256>>>();

    // 4) fused causal flash attention with per-key bias
    attn2_kernel<<<dim3(BATCH * NHEADS, NSEQ / 64), 256, ATTN_SMEM>>>();

    // 5) output projection
    sgemm128<<<dim3(DMODEL / 128, M / 128), 256>>>(att, w_o, out, M, DMODEL, DMODEL);
}

// round 4
// speedup vs baseline: 4.2177x; 1.4293x over previous
#include <cuda_runtime.h>
#include <cuda_bf16.h>
#include <cstdint>
#include <math.h>

#define BATCH   2
#define NSEQ    2048
#define DMODEL  512
#define NHEADS  8
#define DH      64
#define KP      32
#define KEXP    1536
#define TAU_F   6.283185307179586f

// ---------------- scratch (static device memory; no allocations) ----------------
__device__ float g_q[(size_t)BATCH * NHEADS * NSEQ * DH];           // (b,h,n,dh) rotated
__device__ float g_k[(size_t)BATCH * NHEADS * NSEQ * DH];           // (b,h,n,dh) rotated
__device__ float g_v[(size_t)BATCH * NHEADS * NSEQ * DH];           // (b,h,n,dh)
__device__ float g_cos[NHEADS * NSEQ * KP];
__device__ float g_sin[NHEADS * NSEQ * KP];
__device__ float g_bias[NHEADS * NSEQ];                             // lam*S_n/KP per head
__device__ float g_att[(size_t)BATCH * NSEQ * DMODEL];              // (b,n,h*dh)
__device__ __nv_bfloat16 g_aexp[(size_t)BATCH * NSEQ * KEXP];       // A' 4096x1536
__device__ __nv_bfloat16 g_bexp[(size_t)3 * DMODEL * KEXP];         // B' 1536x1536
__device__ __nv_bfloat16 g_bexp2[(size_t)DMODEL * KEXP];            // B2' 512x1536

__constant__ float c_zim[KP] = {
    14.134725142f, 21.022039639f, 25.01085758f,  30.424876126f,
    32.935061588f, 37.586178159f, 40.918719012f, 43.327073281f,
    48.005150881f, 49.773832478f, 52.970321478f, 56.446247697f,
    59.347044003f, 60.831778525f, 65.112544048f, 67.079810529f,
    69.546401711f, 72.067157674f, 75.704690699f, 77.144840069f,
    79.33737502f,  82.910380854f, 84.735492981f, 87.425274613f,
    88.809111208f, 92.491899271f, 94.651344041f, 95.870634228f,
    98.831194218f, 101.317851006f, 103.72553804f, 105.446623052f};

// ---------------- warp-MMA helpers (portable sm_80+ path; sm_100 has no tcgen05) ----------------
__device__ __forceinline__ uint32_t smem_u32(const void* p) {
    uint32_t a;
    asm("{ .reg .u64 t; cvta.to.shared.u64 t, %1; cvt.u32.u64 %0, t; }" : "=r"(a) : "l"(p));
    return a;
}
__device__ __forceinline__ void ldsm4(uint32_t* r, uint32_t a) {
    asm volatile("ldmatrix.sync.aligned.m8n8.x4.shared.b16 {%0,%1,%2,%3}, [%4];"
                 : "=r"(r[0]), "=r"(r[1]), "=r"(r[2]), "=r"(r[3]) : "r"(a));
}
__device__ __forceinline__ void mma16816(float* c, const uint32_t* a, uint32_t b0, uint32_t b1) {
    asm volatile("mma.sync.aligned.m16n8k16.row.col.f32.bf16.bf16.f32 "
                 "{%0,%1,%2,%3}, {%4,%5,%6,%7}, {%8,%9}, {%0,%1,%2,%3};"
                 : "+f"(c[0]), "+f"(c[1]), "+f"(c[2]), "+f"(c[3])
                 : "r"(a[0]), "r"(a[1]), "r"(a[2]), "r"(a[3]), "r"(b0), "r"(b1));
}

// ---------------- bf16 mma GEMM: C[M,Ntot] = A'[M,1536] @ B'[Ntot,1536]^T ----------------
// EPI 0: rotate epilogue -> g_q/g_k/g_v ; EPI 1: plain store to C.
#define KT (KEXP / 32)
// swizzled byte offset within a 128x32-bf16 tile (64B rows)
#define SWZ(r, bc) ((uint32_t)((r) * 64 + ((bc) ^ ((((r) >> 1) & 3) << 4))))

template <int EPI>
__global__ __launch_bounds__(256) void mmagemm(const __nv_bfloat16* __restrict__ A,
                                               const __nv_bfloat16* __restrict__ Bm,
                                               float* __restrict__ C, int Ntot) {
    __shared__ __align__(1024) __nv_bfloat16 As[2][128 * 32];
    __shared__ __align__(1024) __nv_bfloat16 Bs[2][128 * 32];

    const int tid = threadIdx.x;
    const int lane = tid & 31;
    const int wid = tid >> 5;
    const int wm = (wid & 1) * 64;       // warp m-offset within tile
    const int wn = (wid >> 1) * 32;      // warp n-offset within tile
    const int row0 = blockIdx.y * 128;
    const int col0 = blockIdx.x * 128;
    const uint32_t sA = smem_u32(As);
    const uint32_t sB = smem_u32(Bs);

    // per-lane ldmatrix address components
    const int lr = (lane & 7) + ((lane >> 3) & 1) * 8;   // row within 16-row group
    const int kh = (lane >> 4) * 16;                     // k-half byte offset
    uint32_t aoff[4][2], boff[2][2];
#pragma unroll
    for (int mi = 0; mi < 4; mi++)
#pragma unroll
        for (int ks = 0; ks < 2; ks++) {
            int r = wm + mi * 16 + lr;
            aoff[mi][ks] = SWZ(r, ks * 32 + kh);
        }
#pragma unroll
    for (int g = 0; g < 2; g++)
#pragma unroll
        for (int ks = 0; ks < 2; ks++) {
            int r = wn + g * 16 + lr;
            boff[g][ks] = SWZ(r, ks * 32 + kh);
        }

    uint4 ra[2], rb[2];
    const int r_ld0 = tid >> 2, cu_ld = tid & 3;         // ldg/sts mapping
    const int r_ld1 = r_ld0 + 64;

    // preload k-tile 0
    {
        ra[0] = *reinterpret_cast<const uint4*>(&A[(size_t)(row0 + r_ld0) * KEXP + cu_ld * 8]);
        rb[0] = *reinterpret_cast<const uint4*>(&Bm[(size_t)(col0 + r_ld0) * KEXP + cu_ld * 8]);
        ra[1] = *reinterpret_cast<const uint4*>(&A[(size_t)(row0 + r_ld1) * KEXP + cu_ld * 8]);
        rb[1] = *reinterpret_cast<const uint4*>(&Bm[(size_t)(col0 + r_ld1) * KEXP + cu_ld * 8]);
    }
    {
        uint32_t o0 = SWZ(r_ld0, cu_ld * 16), o1 = SWZ(r_ld1, cu_ld * 16);
        *reinterpret_cast<uint4*>((char*)As[0] + o0) = ra[0];
        *reinterpret_cast<uint4*>((char*)Bs[0] + o0) = rb[0];
        *reinterpret_cast<uint4*>((char*)As[0] + o1) = ra[1];
        *reinterpret_cast<uint4*>((char*)Bs[0] + o1) = rb[1];
    }

    float acc[4][4][4];
#pragma unroll
    for (int mi = 0; mi < 4; mi++)
#pragma unroll
        for (int ni = 0; ni < 4; ni++)
#pragma unroll
            for (int q = 0; q < 4; q++) acc[mi][ni][q] = 0.0f;

    for (int t = 0; t < KT; t++) {
        __syncthreads();
        if (t + 1 < KT) {
            int k0 = (t + 1) * 32;
            ra[0] = *reinterpret_cast<const uint4*>(&A[(size_t)(row0 + r_ld0) * KEXP + k0 + cu_ld * 8]);
            rb[0] = *reinterpret_cast<const uint4*>(&Bm[(size_t)(col0 + r_ld0) * KEXP + k0 + cu_ld * 8]);
            ra[1] = *reinterpret_cast<const uint4*>(&A[(size_t)(row0 + r_ld1) * KEXP + k0 + cu_ld * 8]);
            rb[1] = *reinterpret_cast<const uint4*>(&Bm[(size_t)(col0 + r_ld1) * KEXP + k0 + cu_ld * 8]);
        }
        const uint32_t baseA = sA + (uint32_t)((t & 1) * 8192);
        const uint32_t baseB = sB + (uint32_t)((t & 1) * 8192);
#pragma unroll
        for (int ks = 0; ks < 2; ks++) {
            uint32_t af[4][4], bf[2][4];
#pragma unroll
            for (int mi = 0; mi < 4; mi++) ldsm4(af[mi], baseA + aoff[mi][ks]);
#pragma unroll
            for (int g = 0; g < 2; g++) ldsm4(bf[g], baseB + boff[g][ks]);
#pragma unroll
            for (int mi = 0; mi < 4; mi++)
#pragma unroll
                for (int ni = 0; ni < 4; ni++)
                    mma16816(acc[mi][ni], af[mi], bf[ni >> 1][ni & 1], bf[ni >> 1][(ni & 1) + 2]);
        }
        if (t + 1 < KT) {
            int st = (t + 1) & 1;
            uint32_t o0 = SWZ(r_ld0, cu_ld * 16), o1 = SWZ(r_ld1, cu_ld * 16);
            *reinterpret_cast<uint4*>((char*)As[st] + o0) = ra[0];
            *reinterpret_cast<uint4*>((char*)Bs[st] + o0) = rb[0];
            *reinterpret_cast<uint4*>((char*)As[st] + o1) = ra[1];
            *reinterpret_cast<uint4*>((char*)Bs[st] + o1) = rb[1];
        }
    }

    // epilogue: fragment (mi,ni): c0,c1 at (m, n..n+1), c2,c3 at (m+8, n..n+1)
#pragma unroll
    for (int mi = 0; mi < 4; mi++) {
#pragma unroll
        for (int ni = 0; ni < 4; ni++) {
            int m0 = row0 + wm + mi * 16 + (lane >> 2);
            int n = col0 + wn + ni * 8 + (lane & 3) * 2;
#pragma unroll
            for (int half = 0; half < 2; half++) {
                int m = m0 + half * 8;
                float v0 = acc[mi][ni][half * 2 + 0];
                float v1 = acc[mi][ni][half * 2 + 1];
                if (EPI == 1) {
                    *reinterpret_cast<float2*>(&C[(size_t)m * Ntot + n]) = make_float2(v0, v1);
                } else {
                    const int b = m >> 11, nn = m & 2047;
                    const int sect = n >> 9;
                    const int h = (n >> 6) & 7;
                    const int d = n & 63;
                    size_t ob = ((size_t)((b * NHEADS + h) * NSEQ) + nn) * DH + d;
                    if (sect == 2) {
                        *reinterpret_cast<float2*>(&g_v[ob]) = make_float2(v0, v1);
                    } else {
                        int ci = (h * NSEQ + nn) * KP + (d >> 1);
                        float c0 = g_cos[ci], s0 = g_sin[ci];
                        float2 o = make_float2(v0 * c0 - v1 * s0, v0 * s0 + v1 * c0);
                        if (sect == 0) *reinterpret_cast<float2*>(&g_q[ob]) = o;
                        else           *reinterpret_cast<float2*>(&g_k[ob]) = o;
                    }
                }
            }
        }
    }
}

// ---------------- bf16x3 split conversions ----------------
// A' = [hi | lo | hi] along K
__global__ void convA_kernel(const float* __restrict__ src, __nv_bfloat16* __restrict__ dst, int M) {
    int i = blockIdx.x * blockDim.x + threadIdx.x;
    if (i >= M * 128) return;
    int row = i >> 7, c4 = (i & 127) * 4;
    float4 v = *reinterpret_cast<const float4*>(&src[(size_t)row * DMODEL + c4]);
    __nv_bfloat16 h0 = __float2bfloat16(v.x), h1 = __float2bfloat16(v.y);
    __nv_bfloat16 h2 = __float2bfloat16(v.z), h3 = __float2bfloat16(v.w);
    __nv_bfloat16 l0 = __float2bfloat16(v.x - __bfloat162float(h0));
    __nv_bfloat16 l1 = __float2bfloat16(v.y - __bfloat162float(h1));
    __nv_bfloat16 l2 = __float2bfloat16(v.z - __bfloat162float(h2));
    __nv_bfloat16 l3 = __float2bfloat16(v.w - __bfloat162float(h3));
    size_t base = (size_t)row * KEXP + c4;
    __nv_bfloat162* d0 = reinterpret_cast<__nv_bfloat162*>(&dst[base]);
    __nv_bfloat162* d1 = reinterpret_cast<__nv_bfloat162*>(&dst[base + 512]);
    __nv_bfloat162* d2 = reinterpret_cast<__nv_bfloat162*>(&dst[base + 1024]);
    d0[0] = __nv_bfloat162(h0, h1); d0[1] = __nv_bfloat162(h2, h3);
    d1[0] = __nv_bfloat162(l0, l1); d1[1] = __nv_bfloat162(l2, l3);
    d2[0] = __nv_bfloat162(h0, h1); d2[1] = __nv_bfloat162(h2, h3);
}

// B' = [hi | hi | lo] along K; src w is (512, N) row-major; dst (N, 1536)
__global__ void convB_kernel(const float* __restrict__ w, __nv_bfloat16* __restrict__ dst, int N) {
    int i = blockIdx.x * blockDim.x + threadIdx.x;
    if (i >= N * DMODEL) return;
    int k = i & 511, n = i >> 9;
    float v = w[(size_t)k * N + n];
    __nv_bfloat16 hi = __float2bfloat16(v);
    __nv_bfloat16 lo = __float2bfloat16(v - __bfloat162float(hi));
    size_t base = (size_t)n * KEXP + k;
    dst[base] = hi;
    dst[base + 512] = hi;
    dst[base + 1024] = lo;
}

// ---------------- theta / cos / sin / per-key bias ----------------
__global__ void prep_kernel(const float* __restrict__ log_scale,
                            const float* __restrict__ log_lambda_sigma) {
    int idx = blockIdx.x * blockDim.x + threadIdx.x;
    if (idx >= NHEADS * NSEQ) return;
    int h = idx / NSEQ;
    int n = idx % NSEQ;
    float sc = expf(log_scale[h]);
    float lam = expf(log_lambda_sigma[h]);
    float tau = log1pf((float)n);
    float ssum = 0.0f;
#pragma unroll
    for (int p = 0; p < KP; p++) {
        float g = c_zim[p] / c_zim[0];
        float th = tau * g * sc;
        g_cos[idx * KP + p] = cosf(th);
        g_sin[idx * KP + p] = sinf(th);
        ssum += floorf(th / TAU_F);
    }
    g_bias[idx] = lam * ssum * (1.0f / KP);
}

// ---------------- fused causal flash attention, register-tiled (fp32) ----------------
#define PSTR 68
__global__ __launch_bounds__(256, 2) void attn2_kernel() {
    extern __shared__ float sm[];
    float* qT = sm;
    float* kT = sm + 64 * PSTR;
    float* vs = sm + 128 * PSTR;
    float* ps = sm + 192 * PSTR;
    float* bs = sm + 256 * PSTR;

    const int tid = threadIdx.x;
    const int tx = tid & 15;
    const int ty = tid >> 4;
    const int bh = blockIdx.x;
    const int h = bh & (NHEADS - 1);
    const int b = bh >> 3;
    const int qbase = (int)(gridDim.y - 1 - blockIdx.y) << 6;

    const float* qp = g_q + (size_t)bh * NSEQ * DH;
    const float* kp = g_k + (size_t)bh * NSEQ * DH;
    const float* vp = g_v + (size_t)bh * NSEQ * DH;
    const float* bp = g_bias + h * NSEQ;

    for (int idx = tid; idx < 1024; idx += 256) {
        int dq = idx >> 6, j = idx & 63;
        float4 a = *reinterpret_cast<const float4*>(&qp[(size_t)(qbase + j) * DH + 4 * dq]);
        qT[(4 * dq + 0) * PSTR + j] = a.x;
        qT[(4 * dq + 1) * PSTR + j] = a.y;
        qT[(4 * dq + 2) * PSTR + j] = a.z;
        qT[(4 * dq + 3) * PSTR + j] = a.w;
    }

    float m[4], l[4], o[4][4];
#pragma unroll
    for (int i = 0; i < 4; i++) {
        m[i] = -INFINITY; l[i] = 0.0f;
#pragma unroll
        for (int j = 0; j < 4; j++) o[i][j] = 0.0f;
    }

    const int ntiles = (qbase >> 6) + 1;
    for (int t = 0; t < ntiles; t++) {
        const int jg = t << 6;
        __syncthreads();
        for (int idx = tid; idx < 1024; idx += 256) {
            int dq = idx >> 6, j = idx & 63;
            float4 a = *reinterpret_cast<const float4*>(&kp[(size_t)(jg + j) * DH + 4 * dq]);
            kT[(4 * dq + 0) * PSTR + j] = a.x;
            kT[(4 * dq + 1) * PSTR + j] = a.y;
            kT[(4 * dq + 2) * PSTR + j] = a.z;
            kT[(4 * dq + 3) * PSTR + j] = a.w;
        }
        for (int idx = tid; idx < 1024; idx += 256) {
            int j = idx >> 4, dq = idx & 15;
            *reinterpret_cast<float4*>(&vs[j * PSTR + 4 * dq]) =
                *reinterpret_cast<const float4*>(&vp[(size_t)(jg + j) * DH + 4 * dq]);
        }
        if (tid < 64) bs[tid] = bp[jg + tid];
        __syncthreads();

        float s[4][4];
#pragma unroll
        for (int i = 0; i < 4; i++)
#pragma unroll
            for (int j = 0; j < 4; j++) s[i][j] = 0.0f;
#pragma unroll
        for (int d = 0; d < DH; d++) {
            float4 qa = *reinterpret_cast<const float4*>(&qT[d * PSTR + 4 * ty]);
            float4 kb = *reinterpret_cast<const float4*>(&kT[d * PSTR + 4 * tx]);
            float a[4] = {qa.x, qa.y, qa.z, qa.w};
            float bb[4] = {kb.x, kb.y, kb.z, kb.w};
#pragma unroll
            for (int i = 0; i < 4; i++)
#pragma unroll
                for (int j = 0; j < 4; j++) s[i][j] += a[i] * bb[j];
        }

        float bj[4] = {bs[4 * tx], bs[4 * tx + 1], bs[4 * tx + 2], bs[4 * tx + 3]};
        const bool diag = (jg == qbase);
#pragma unroll
        for (int i = 0; i < 4; i++)
#pragma unroll
            for (int j = 0; j < 4; j++) {
                float val = s[i][j] * 0.125f + bj[j];
                if (diag && (4 * tx + j > 4 * ty + i)) val = -INFINITY;
                s[i][j] = val;
            }

#pragma unroll
        for (int i = 0; i < 4; i++) {
            float mi = fmaxf(fmaxf(s[i][0], s[i][1]), fmaxf(s[i][2], s[i][3]));
#pragma unroll
            for (int off = 8; off; off >>= 1)
                mi = fmaxf(mi, __shfl_xor_sync(0xffffffffu, mi, off));
            float mn = fmaxf(m[i], mi);
            float corr = __expf(m[i] - mn);
            m[i] = mn;
            float p0 = __expf(s[i][0] - mn);
            float p1 = __expf(s[i][1] - mn);
            float p2 = __expf(s[i][2] - mn);
            float p3 = __expf(s[i][3] - mn);
            float ls = p0 + p1 + p2 + p3;
#pragma unroll
            for (int off = 8; off; off >>= 1)
                ls += __shfl_xor_sync(0xffffffffu, ls, off);
            l[i] = l[i] * corr + ls;
            o[i][0] *= corr; o[i][1] *= corr; o[i][2] *= corr; o[i][3] *= corr;
            *reinterpret_cast<float4*>(&ps[(4 * ty + i) * PSTR + 4 * tx]) =
                make_float4(p0, p1, p2, p3);
        }
        __syncwarp();

#pragma unroll
        for (int kb4 = 0; kb4 < 16; kb4++) {
            float4 p4[4], vv[4];
#pragma unroll
            for (int i = 0; i < 4; i++)
                p4[i] = *reinterpret_cast<const float4*>(&ps[(4 * ty + i) * PSTR + 4 * kb4]);
#pragma unroll
            for (int c = 0; c < 4; c++)
                vv[c] = *reinterpret_cast<const float4*>(&vs[(4 * kb4 + c) * PSTR + 4 * tx]);
#pragma unroll
            for (int i = 0; i < 4; i++) {
                float pc[4] = {p4[i].x, p4[i].y, p4[i].z, p4[i].w};
#pragma unroll
                for (int c = 0; c < 4; c++) {
                    o[i][0] += pc[c] * vv[c].x;
                    o[i][1] += pc[c] * vv[c].y;
                    o[i][2] += pc[c] * vv[c].z;
                    o[i][3] += pc[c] * vv[c].w;
                }
            }
        }
    }

#pragma unroll
    for (int i = 0; i < 4; i++) {
        float inv = 1.0f / l[i];
        size_t ob = ((size_t)(b * NSEQ + qbase + 4 * ty + i)) * DMODEL + h * DH + 4 * tx;
        *reinterpret_cast<float4*>(&g_att[ob]) =
            make_float4(o[i][0] * inv, o[i][1] * inv, o[i][2] * inv, o[i][3] * inv);
    }
}

// ---------------- launch ----------------
extern "C" void kernel_launch(void* const* d_in, const int* in_sizes, int n_in,
                              void* d_out, int out_size) {
    const float* x      = (const float*)d_in[0];
    const float* w_qkv  = (const float*)d_in[1];
    const float* w_o    = (const float*)d_in[2];
    const float* lscale = (const float*)d_in[3];
    const float* lls    = (const float*)d_in[4];
    float* out = (float*)d_out;

    float* att;
    __nv_bfloat16 *aexp, *bexp, *bexp2;
    cudaGetSymbolAddress((void**)&att, g_att);
    cudaGetSymbolAddress((void**)&aexp, g_aexp);
    cudaGetSymbolAddress((void**)&bexp, g_bexp);
    cudaGetSymbolAddress((void**)&bexp2, g_bexp2);

    const int M = BATCH * NSEQ;   // 4096
    const int ATTN_SMEM = (256 * PSTR + 64) * (int)sizeof(float);
    cudaFuncSetAttribute(attn2_kernel, cudaFuncAttributeMaxDynamicSharedMemorySize, ATTN_SMEM);

    // 1) theta/cos/sin + per-key bias (needed by GEMM1 epilogue)
    prep_kernel<<<(NHEADS * NSEQ + 127) / 128, 128>>>(lscale, lls);

    // 2) bf16x3 conversions for QKV GEMM
    convA_kernel<<<(M * 128 + 255) / 256, 256>>>(x, aexp, M);
    convB_kernel<<<(3 * DMODEL * DMODEL + 255) / 256, 256>>>(w_qkv, bexp, 3 * DMODEL);

    // 3) QKV projection on mma.sync, rotation fused in epilogue -> g_q/g_k/g_v
    mmagemm<0><<<dim3(3 * DMODEL / 128, M / 128), 256>>>(aexp, bexp, nullptr, 3 * DMODEL);

    // 4) fused causal flash attention with per-key bias
    attn2_kernel<<<dim3(BATCH * NHEADS, NSEQ / 64), 256, ATTN_SMEM>>>();

    // 5) output projection on mma.sync
    convA_kernel<<<(M * 128 + 255) / 256, 256>>>(att, aexp, M);
    convB_kernel<<<(DMODEL * DMODEL + 255) / 256, 256>>>(w_o, bexp2, DMODEL);
    mmagemm<1><<<dim3(DMODEL / 128, M / 128), 256>>>(aexp, bexp2, out, DMODEL);
}

// round 5
// speedup vs baseline: 6.7201x; 1.5933x over previous
#include <cuda_runtime.h>
#include <cuda_bf16.h>
#include <cstdint>
#include <math.h>

#define BATCH   2
#define NSEQ    2048
#define DMODEL  512
#define NHEADS  8
#define DH      64
#define KP      32
#define KEXP    1536
#define TAU_F   6.283185307179586f

// ---------------- scratch (static device memory; no allocations) ----------------
__device__ __nv_bfloat16 g_qe[(size_t)BATCH * NHEADS * NSEQ * 192];  // [qh|ql|qh]
__device__ __nv_bfloat16 g_ke[(size_t)BATCH * NHEADS * NSEQ * 192];  // [kh|kh|kl]
__device__ __nv_bfloat16 g_vh[(size_t)BATCH * NHEADS * NSEQ * DH];
__device__ __nv_bfloat16 g_vl[(size_t)BATCH * NHEADS * NSEQ * DH];
__device__ float g_cos[NHEADS * NSEQ * KP];
__device__ float g_sin[NHEADS * NSEQ * KP];
__device__ float g_bias[NHEADS * NSEQ];                             // lam*S_n/KP per head
__device__ float g_att[(size_t)BATCH * NSEQ * DMODEL];              // (b,n,h*dh)
__device__ __nv_bfloat16 g_aexp[(size_t)BATCH * NSEQ * KEXP];       // A' 4096x1536
__device__ __nv_bfloat16 g_bexp[(size_t)3 * DMODEL * KEXP];         // B' 1536x1536
__device__ __nv_bfloat16 g_bexp2[(size_t)DMODEL * KEXP];            // B2' 512x1536

__constant__ float c_zim[KP] = {
    14.134725142f, 21.022039639f, 25.01085758f,  30.424876126f,
    32.935061588f, 37.586178159f, 40.918719012f, 43.327073281f,
    48.005150881f, 49.773832478f, 52.970321478f, 56.446247697f,
    59.347044003f, 60.831778525f, 65.112544048f, 67.079810529f,
    69.546401711f, 72.067157674f, 75.704690699f, 77.144840069f,
    79.33737502f,  82.910380854f, 84.735492981f, 87.425274613f,
    88.809111208f, 92.491899271f, 94.651344041f, 95.870634228f,
    98.831194218f, 101.317851006f, 103.72553804f, 105.446623052f};

// ---------------- warp-MMA / async helpers (portable sm_80+ path) ----------------
__device__ __forceinline__ uint32_t smem_u32(const void* p) {
    uint32_t a;
    asm("{ .reg .u64 t; cvta.to.shared.u64 t, %1; cvt.u32.u64 %0, t; }" : "=r"(a) : "l"(p));
    return a;
}
__device__ __forceinline__ void ldsm4(uint32_t* r, uint32_t a) {
    asm volatile("ldmatrix.sync.aligned.m8n8.x4.shared.b16 {%0,%1,%2,%3}, [%4];"
                 : "=r"(r[0]), "=r"(r[1]), "=r"(r[2]), "=r"(r[3]) : "r"(a));
}
__device__ __forceinline__ void ldsm4t(uint32_t* r, uint32_t a) {
    asm volatile("ldmatrix.sync.aligned.m8n8.x4.trans.shared.b16 {%0,%1,%2,%3}, [%4];"
                 : "=r"(r[0]), "=r"(r[1]), "=r"(r[2]), "=r"(r[3]) : "r"(a));
}
__device__ __forceinline__ void mma16816(float* c, const uint32_t* a, uint32_t b0, uint32_t b1) {
    asm volatile("mma.sync.aligned.m16n8k16.row.col.f32.bf16.bf16.f32 "
                 "{%0,%1,%2,%3}, {%4,%5,%6,%7}, {%8,%9}, {%0,%1,%2,%3};"
                 : "+f"(c[0]), "+f"(c[1]), "+f"(c[2]), "+f"(c[3])
                 : "r"(a[0]), "r"(a[1]), "r"(a[2]), "r"(a[3]), "r"(b0), "r"(b1));
}
__device__ __forceinline__ void cpasync16(uint32_t dst, const void* src) {
    asm volatile("cp.async.cg.shared.global [%0], [%1], 16;" :: "r"(dst), "l"(src));
}
__device__ __forceinline__ void cpcommit() {
    asm volatile("cp.async.commit_group;");
}
template <int N>
__device__ __forceinline__ void cpwait() {
    asm volatile("cp.async.wait_group %0;" :: "n"(N));
}

// ---------------- bf16 mma GEMM: C[M,Ntot] = A'[M,1536] @ B'[Ntot,1536]^T ----------------
#define KT (KEXP / 32)
#define SWZ(r, bc) ((uint32_t)((r) * 64 + ((bc) ^ ((((r) >> 1) & 3) << 4))))

template <int EPI>
__global__ __launch_bounds__(256) void mmagemm(const __nv_bfloat16* __restrict__ A,
                                               const __nv_bfloat16* __restrict__ Bm,
                                               float* __restrict__ C, int Ntot) {
    __shared__ __align__(1024) __nv_bfloat16 As[2][128 * 32];
    __shared__ __align__(1024) __nv_bfloat16 Bs[2][128 * 32];

    const int tid = threadIdx.x;
    const int lane = tid & 31;
    const int wid = tid >> 5;
    const int wm = (wid & 1) * 64;
    const int wn = (wid >> 1) * 32;
    const int row0 = blockIdx.y * 128;
    const int col0 = blockIdx.x * 128;
    const uint32_t sA = smem_u32(As);
    const uint32_t sB = smem_u32(Bs);

    const int lr = (lane & 7) + ((lane >> 3) & 1) * 8;
    const int kh = (lane >> 4) * 16;
    uint32_t aoff[4][2], boff[2][2];
#pragma unroll
    for (int mi = 0; mi < 4; mi++)
#pragma unroll
        for (int ks = 0; ks < 2; ks++) aoff[mi][ks] = SWZ(wm + mi * 16 + lr, ks * 32 + kh);
#pragma unroll
    for (int g = 0; g < 2; g++)
#pragma unroll
        for (int ks = 0; ks < 2; ks++) boff[g][ks] = SWZ(wn + g * 16 + lr, ks * 32 + kh);

    uint4 ra[2], rb[2];
    const int r_ld0 = tid >> 2, cu_ld = tid & 3;
    const int r_ld1 = r_ld0 + 64;

    ra[0] = *reinterpret_cast<const uint4*>(&A[(size_t)(row0 + r_ld0) * KEXP + cu_ld * 8]);
    rb[0] = *reinterpret_cast<const uint4*>(&Bm[(size_t)(col0 + r_ld0) * KEXP + cu_ld * 8]);
    ra[1] = *reinterpret_cast<const uint4*>(&A[(size_t)(row0 + r_ld1) * KEXP + cu_ld * 8]);
    rb[1] = *reinterpret_cast<const uint4*>(&Bm[(size_t)(col0 + r_ld1) * KEXP + cu_ld * 8]);
    {
        uint32_t o0 = SWZ(r_ld0, cu_ld * 16), o1 = SWZ(r_ld1, cu_ld * 16);
        *reinterpret_cast<uint4*>((char*)As[0] + o0) = ra[0];
        *reinterpret_cast<uint4*>((char*)Bs[0] + o0) = rb[0];
        *reinterpret_cast<uint4*>((char*)As[0] + o1) = ra[1];
        *reinterpret_cast<uint4*>((char*)Bs[0] + o1) = rb[1];
    }

    float acc[4][4][4];
#pragma unroll
    for (int mi = 0; mi < 4; mi++)
#pragma unroll
        for (int ni = 0; ni < 4; ni++)
#pragma unroll
            for (int q = 0; q < 4; q++) acc[mi][ni][q] = 0.0f;

    for (int t = 0; t < KT; t++) {
        __syncthreads();
        if (t + 1 < KT) {
            int k0 = (t + 1) * 32;
            ra[0] = *reinterpret_cast<const uint4*>(&A[(size_t)(row0 + r_ld0) * KEXP + k0 + cu_ld * 8]);
            rb[0] = *reinterpret_cast<const uint4*>(&Bm[(size_t)(col0 + r_ld0) * KEXP + k0 + cu_ld * 8]);
            ra[1] = *reinterpret_cast<const uint4*>(&A[(size_t)(row0 + r_ld1) * KEXP + k0 + cu_ld * 8]);
            rb[1] = *reinterpret_cast<const uint4*>(&Bm[(size_t)(col0 + r_ld1) * KEXP + k0 + cu_ld * 8]);
        }
        const uint32_t baseA = sA + (uint32_t)((t & 1) * 8192);
        const uint32_t baseB = sB + (uint32_t)((t & 1) * 8192);
#pragma unroll
        for (int ks = 0; ks < 2; ks++) {
            uint32_t af[4][4], bf[2][4];
#pragma unroll
            for (int mi = 0; mi < 4; mi++) ldsm4(af[mi], baseA + aoff[mi][ks]);
#pragma unroll
            for (int g = 0; g < 2; g++) ldsm4(bf[g], baseB + boff[g][ks]);
#pragma unroll
            for (int mi = 0; mi < 4; mi++)
#pragma unroll
                for (int ni = 0; ni < 4; ni++)
                    mma16816(acc[mi][ni], af[mi], bf[ni >> 1][ni & 1], bf[ni >> 1][(ni & 1) + 2]);
        }
        if (t + 1 < KT) {
            int st = (t + 1) & 1;
            uint32_t o0 = SWZ(r_ld0, cu_ld * 16), o1 = SWZ(r_ld1, cu_ld * 16);
            *reinterpret_cast<uint4*>((char*)As[st] + o0) = ra[0];
            *reinterpret_cast<uint4*>((char*)Bs[st] + o0) = rb[0];
            *reinterpret_cast<uint4*>((char*)As[st] + o1) = ra[1];
            *reinterpret_cast<uint4*>((char*)Bs[st] + o1) = rb[1];
        }
    }

#pragma unroll
    for (int mi = 0; mi < 4; mi++) {
#pragma unroll
        for (int ni = 0; ni < 4; ni++) {
            int m0 = row0 + wm + mi * 16 + (lane >> 2);
            int n = col0 + wn + ni * 8 + (lane & 3) * 2;
#pragma unroll
            for (int half = 0; half < 2; half++) {
                int m = m0 + half * 8;
                float v0 = acc[mi][ni][half * 2 + 0];
                float v1 = acc[mi][ni][half * 2 + 1];
                if (EPI == 1) {
                    *reinterpret_cast<float2*>(&C[(size_t)m * Ntot + n]) = make_float2(v0, v1);
                } else {
                    const int bb = m >> 11, nn = m & 2047;
                    const int sect = n >> 9;
                    const int h = (n >> 6) & 7;
                    const int d = n & 63;
                    if (sect == 2) {
                        __nv_bfloat162 hi = __float22bfloat162_rn(make_float2(v0, v1));
                        __nv_bfloat162 lo = __float22bfloat162_rn(
                            make_float2(v0 - __low2float(hi), v1 - __high2float(hi)));
                        size_t vb = ((size_t)((bb * NHEADS + h) * NSEQ) + nn) * DH + d;
                        *reinterpret_cast<__nv_bfloat162*>(&g_vh[vb]) = hi;
                        *reinterpret_cast<__nv_bfloat162*>(&g_vl[vb]) = lo;
                    } else {
                        int ci = (h * NSEQ + nn) * KP + (d >> 1);
                        float c0 = g_cos[ci], s0 = g_sin[ci];
                        float o0 = v0 * c0 - v1 * s0;
                        float o1 = v0 * s0 + v1 * c0;
                        __nv_bfloat162 hi = __float22bfloat162_rn(make_float2(o0, o1));
                        __nv_bfloat162 lo = __float22bfloat162_rn(
                            make_float2(o0 - __low2float(hi), o1 - __high2float(hi)));
                        size_t qb = ((size_t)((bb * NHEADS + h) * NSEQ) + nn) * 192 + d;
                        if (sect == 0) {   // Q: [hi | lo | hi]
                            *reinterpret_cast<__nv_bfloat162*>(&g_qe[qb]) = hi;
                            *reinterpret_cast<__nv_bfloat162*>(&g_qe[qb + 64]) = lo;
                            *reinterpret_cast<__nv_bfloat162*>(&g_qe[qb + 128]) = hi;
                        } else {           // K: [hi | hi | lo]
                            *reinterpret_cast<__nv_bfloat162*>(&g_ke[qb]) = hi;
                            *reinterpret_cast<__nv_bfloat162*>(&g_ke[qb + 64]) = hi;
                            *reinterpret_cast<__nv_bfloat162*>(&g_ke[qb + 128]) = lo;
                        }
                    }
                }
            }
        }
    }
}

// ---------------- bf16x3 split conversions ----------------
__global__ void convA_kernel(const float* __restrict__ src, __nv_bfloat16* __restrict__ dst, int M) {
    int i = blockIdx.x * blockDim.x + threadIdx.x;
    if (i >= M * 128) return;
    int row = i >> 7, c4 = (i & 127) * 4;
    float4 v = *reinterpret_cast<const float4*>(&src[(size_t)row * DMODEL + c4]);
    __nv_bfloat16 h0 = __float2bfloat16(v.x), h1 = __float2bfloat16(v.y);
    __nv_bfloat16 h2 = __float2bfloat16(v.z), h3 = __float2bfloat16(v.w);
    __nv_bfloat16 l0 = __float2bfloat16(v.x - __bfloat162float(h0));
    __nv_bfloat16 l1 = __float2bfloat16(v.y - __bfloat162float(h1));
    __nv_bfloat16 l2 = __float2bfloat16(v.z - __bfloat162float(h2));
    __nv_bfloat16 l3 = __float2bfloat16(v.w - __bfloat162float(h3));
    size_t base = (size_t)row * KEXP + c4;
    __nv_bfloat162* d0 = reinterpret_cast<__nv_bfloat162*>(&dst[base]);
    __nv_bfloat162* d1 = reinterpret_cast<__nv_bfloat162*>(&dst[base + 512]);
    __nv_bfloat162* d2 = reinterpret_cast<__nv_bfloat162*>(&dst[base + 1024]);
    d0[0] = __nv_bfloat162(h0, h1); d0[1] = __nv_bfloat162(h2, h3);
    d1[0] = __nv_bfloat162(l0, l1); d1[1] = __nv_bfloat162(l2, l3);
    d2[0] = __nv_bfloat162(h0, h1); d2[1] = __nv_bfloat162(h2, h3);
}

__global__ void convB_kernel(const float* __restrict__ w, __nv_bfloat16* __restrict__ dst, int N) {
    int i = blockIdx.x * blockDim.x + threadIdx.x;
    if (i >= N * DMODEL) return;
    int k = i & 511, n = i >> 9;
    float v = w[(size_t)k * N + n];
    __nv_bfloat16 hi = __float2bfloat16(v);
    __nv_bfloat16 lo = __float2bfloat16(v - __bfloat162float(hi));
    size_t base = (size_t)n * KEXP + k;
    dst[base] = hi;
    dst[base + 512] = hi;
    dst[base + 1024] = lo;
}

// ---------------- theta / cos / sin / per-key bias ----------------
__global__ void prep_kernel(const float* __restrict__ log_scale,
                            const float* __restrict__ log_lambda_sigma) {
    int idx = blockIdx.x * blockDim.x + threadIdx.x;
    if (idx >= NHEADS * NSEQ) return;
    int h = idx / NSEQ;
    int n = idx % NSEQ;
    float sc = expf(log_scale[h]);
    float lam = expf(log_lambda_sigma[h]);
    float tau = log1pf((float)n);
    float ssum = 0.0f;
#pragma unroll
    for (int p = 0; p < KP; p++) {
        float g = c_zim[p] / c_zim[0];
        float th = tau * g * sc;
        g_cos[idx * KP + p] = cosf(th);
        g_sin[idx * KP + p] = sinf(th);
        ssum += floorf(th / TAU_F);
    }
    g_bias[idx] = lam * ssum * (1.0f / KP);
}

// ---------------- tensor-core flash attention (bf16 split-compensated) ----------------
// Block: 256 thr (8 warps), 128 query rows; key tiles of 64; K-dim 192 (split).
// SMEM (bytes): Q' 128x400, per stage: K' 64x400, Vh 64x144, Vl 64x144, bias 256.
#define QOFF   0
#define QSZ    (128 * 400)
#define STSZ   (64 * 400 + 2 * 64 * 144 + 256)
#define KOFF(s)  (QSZ + (s) * STSZ)
#define VHOFF(s) (KOFF(s) + 64 * 400)
#define VLOFF(s) (VHOFF(s) + 64 * 144)
#define BOFF(s)  (VLOFF(s) + 64 * 144)
#define ATT_SMEM (QSZ + 2 * STSZ)

__global__ __launch_bounds__(256) void attn3_kernel() {
    extern __shared__ char smc[];
    const uint32_t smb = smem_u32(smc);
    const int tid = threadIdx.x;
    const int lane = tid & 31;
    const int wid = tid >> 5;
    const int bh = blockIdx.x;
    const int h = bh & (NHEADS - 1);
    const int b = bh >> 3;
    const int qbase = (15 - (int)blockIdx.y) << 7;
    const int ntiles = (qbase >> 6) + 2;

    const __nv_bfloat16* qe = g_qe + (size_t)bh * NSEQ * 192;
    const __nv_bfloat16* ke = g_ke + (size_t)bh * NSEQ * 192;
    const __nv_bfloat16* vh = g_vh + (size_t)bh * NSEQ * DH;
    const __nv_bfloat16* vl = g_vl + (size_t)bh * NSEQ * DH;
    const float* bp = g_bias + h * NSEQ;

    // ---- async load of Q' (group 0, with tile 0) ----
    for (int i = tid; i < 3072; i += 256) {
        int r = i / 24, c = i % 24;
        cpasync16(smb + QOFF + r * 400 + c * 16, qe + (size_t)(qbase + r) * 192 + c * 8);
    }
    // tile loader
    auto load_tile = [&](int t, int st) {
        int jg = t << 6;
#pragma unroll
        for (int q = 0; q < 6; q++) {
            int i = q * 256 + tid, r = i / 24, c = i % 24;
            cpasync16(smb + KOFF(st) + r * 400 + c * 16, ke + (size_t)(jg + r) * 192 + c * 8);
        }
#pragma unroll
        for (int q = 0; q < 2; q++) {
            int i = q * 256 + tid, r = i >> 3, c = i & 7;
            cpasync16(smb + VHOFF(st) + r * 144 + c * 16, vh + (size_t)(jg + r) * DH + c * 8);
            cpasync16(smb + VLOFF(st) + r * 144 + c * 16, vl + (size_t)(jg + r) * DH + c * 8);
        }
        if (tid < 16) cpasync16(smb + BOFF(st) + tid * 16, bp + jg + tid * 4);
    };
    load_tile(0, 0);
    cpcommit();
    load_tile(1, 1);
    cpcommit();

    // per-lane ldsm address components (row = lane&15, chunk = lane>>4)
    const uint32_t qaddr = smb + QOFF + (wid * 16 + (lane & 15)) * 400 + (lane >> 4) * 16;
    const uint32_t klocal = (uint32_t)((lane & 15) * 400 + (lane >> 4) * 16);
    const uint32_t vlocal = (uint32_t)((lane & 15) * 144 + (lane >> 4) * 16);

    float o[8][4];
#pragma unroll
    for (int i = 0; i < 8; i++)
#pragma unroll
        for (int q = 0; q < 4; q++) o[i][q] = 0.0f;
    float m0 = -INFINITY, m1 = -INFINITY, l0 = 0.0f, l1 = 0.0f;
    const int qm0 = qbase + wid * 16 + (lane >> 2);
    const int qm1 = qm0 + 8;

    for (int t = 0; t < ntiles; t++) {
        if (t < ntiles - 1) cpwait<1>(); else cpwait<0>();
        __syncthreads();
        const int st = t & 1;
        const int jg = t << 6;

        // ---- S = Q' K'^T ----
        float s[8][4];
#pragma unroll
        for (int i = 0; i < 8; i++)
#pragma unroll
            for (int q = 0; q < 4; q++) s[i][q] = 0.0f;
        const uint32_t kb = smb + KOFF(st);
#pragma unroll
        for (int ks = 0; ks < 12; ks++) {
            uint32_t a[4];
            ldsm4(a, qaddr + ks * 32);
            uint32_t bf[4][4];
#pragma unroll
            for (int ng = 0; ng < 4; ng++) ldsm4(bf[ng], kb + klocal + ng * 6400 + ks * 32);
#pragma unroll
            for (int nf = 0; nf < 8; nf++)
                mma16816(s[nf], a, bf[nf >> 1][nf & 1], bf[nf >> 1][(nf & 1) + 2]);
        }

        // ---- bias + scale + mask ----
        const bool masked = (t >= ntiles - 2);
#pragma unroll
        for (int nf = 0; nf < 8; nf++) {
            int col = jg + nf * 8 + ((lane & 3) << 1);
            float2 bj = *reinterpret_cast<const float2*>(smc + BOFF(st) + (nf * 8 + ((lane & 3) << 1)) * 4);
            s[nf][0] = s[nf][0] * 0.125f + bj.x;
            s[nf][1] = s[nf][1] * 0.125f + bj.y;
            s[nf][2] = s[nf][2] * 0.125f + bj.x;
            s[nf][3] = s[nf][3] * 0.125f + bj.y;
            if (masked) {
                if (col > qm0)     s[nf][0] = -INFINITY;
                if (col + 1 > qm0) s[nf][1] = -INFINITY;
                if (col > qm1)     s[nf][2] = -INFINITY;
                if (col + 1 > qm1) s[nf][3] = -INFINITY;
            }
        }

        // ---- online softmax ----
        float mx0 = -INFINITY, mx1 = -INFINITY;
#pragma unroll
        for (int nf = 0; nf < 8; nf++) {
            mx0 = fmaxf(mx0, fmaxf(s[nf][0], s[nf][1]));
            mx1 = fmaxf(mx1, fmaxf(s[nf][2], s[nf][3]));
        }
        mx0 = fmaxf(mx0, __shfl_xor_sync(0xffffffffu, mx0, 1));
        mx0 = fmaxf(mx0, __shfl_xor_sync(0xffffffffu, mx0, 2));
        mx1 = fmaxf(mx1, __shfl_xor_sync(0xffffffffu, mx1, 1));
        mx1 = fmaxf(mx1, __shfl_xor_sync(0xffffffffu, mx1, 2));
        float mn0 = fmaxf(m0, mx0), mn1 = fmaxf(m1, mx1);
        float corr0 = __expf(m0 - mn0), corr1 = __expf(m1 - mn1);
        m0 = mn0; m1 = mn1;
        float ps0 = 0.0f, ps1 = 0.0f;
#pragma unroll
        for (int nf = 0; nf < 8; nf++) {
            s[nf][0] = __expf(s[nf][0] - mn0);
            s[nf][1] = __expf(s[nf][1] - mn0);
            s[nf][2] = __expf(s[nf][2] - mn1);
            s[nf][3] = __expf(s[nf][3] - mn1);
            ps0 += s[nf][0] + s[nf][1];
            ps1 += s[nf][2] + s[nf][3];
        }
        ps0 += __shfl_xor_sync(0xffffffffu, ps0, 1);
        ps0 += __shfl_xor_sync(0xffffffffu, ps0, 2);
        ps1 += __shfl_xor_sync(0xffffffffu, ps1, 1);
        ps1 += __shfl_xor_sync(0xffffffffu, ps1, 2);
        l0 = l0 * corr0 + ps0;
        l1 = l1 * corr1 + ps1;
#pragma unroll
        for (int nf = 0; nf < 8; nf++) {
            o[nf][0] *= corr0; o[nf][1] *= corr0;
            o[nf][2] *= corr1; o[nf][3] *= corr1;
        }

        // ---- O += (Ph+Pl) V (split-compensated) ----
        const uint32_t vhb = smb + VHOFF(st);
        const uint32_t vlb = smb + VLOFF(st);
#pragma unroll
        for (int ks2 = 0; ks2 < 4; ks2++) {
            const int f0 = 2 * ks2, f1 = 2 * ks2 + 1;
            __nv_bfloat162 h0 = __float22bfloat162_rn(make_float2(s[f0][0], s[f0][1]));
            __nv_bfloat162 h1 = __float22bfloat162_rn(make_float2(s[f0][2], s[f0][3]));
            __nv_bfloat162 h2 = __float22bfloat162_rn(make_float2(s[f1][0], s[f1][1]));
            __nv_bfloat162 h3 = __float22bfloat162_rn(make_float2(s[f1][2], s[f1][3]));
            __nv_bfloat162 e0 = __float22bfloat162_rn(
                make_float2(s[f0][0] - __low2float(h0), s[f0][1] - __high2float(h0)));
            __nv_bfloat162 e1 = __float22bfloat162_rn(
                make_float2(s[f0][2] - __low2float(h1), s[f0][3] - __high2float(h1)));
            __nv_bfloat162 e2 = __float22bfloat162_rn(
                make_float2(s[f1][0] - __low2float(h2), s[f1][1] - __high2float(h2)));
            __nv_bfloat162 e3 = __float22bfloat162_rn(
                make_float2(s[f1][2] - __low2float(h3), s[f1][3] - __high2float(h3)));
            uint32_t ah[4] = {*(uint32_t*)&h0, *(uint32_t*)&h1, *(uint32_t*)&h2, *(uint32_t*)&h3};
            uint32_t al[4] = {*(uint32_t*)&e0, *(uint32_t*)&e1, *(uint32_t*)&e2, *(uint32_t*)&e3};
#pragma unroll
            for (int dseg = 0; dseg < 4; dseg++) {
                uint32_t bhf[4], blf[4];
                ldsm4t(bhf, vhb + ks2 * 2304 + vlocal + dseg * 32);
                ldsm4t(blf, vlb + ks2 * 2304 + vlocal + dseg * 32);
                mma16816(o[2 * dseg],     ah, bhf[0], bhf[1]);
                mma16816(o[2 * dseg + 1], ah, bhf[2], bhf[3]);
                mma16816(o[2 * dseg],     al, bhf[0], bhf[1]);
                mma16816(o[2 * dseg + 1], al, bhf[2], bhf[3]);
                mma16816(o[2 * dseg],     ah, blf[0], blf[1]);
                mma16816(o[2 * dseg + 1], ah, blf[2], blf[3]);
            }
        }

        __syncthreads();
        if (t + 2 < ntiles) { load_tile(t + 2, st); cpcommit(); }
    }

    // ---- normalize + store ----
    const float inv0 = 1.0f / l0, inv1 = 1.0f / l1;
#pragma unroll
    for (int nf = 0; nf < 8; nf++) {
        int col = h * DH + nf * 8 + ((lane & 3) << 1);
        *reinterpret_cast<float2*>(&g_att[(size_t)(b * NSEQ + qm0) * DMODEL + col]) =
            make_float2(o[nf][0] * inv0, o[nf][1] * inv0);
        *reinterpret_cast<float2*>(&g_att[(size_t)(b * NSEQ + qm1) * DMODEL + col]) =
            make_float2(o[nf][2] * inv1, o[nf][3] * inv1);
    }
}

// ---------------- launch ----------------
extern "C" void kernel_launch(void* const* d_in, const int* in_sizes, int n_in,
                              void* d_out, int out_size) {
    const float* x      = (const float*)d_in[0];
    const float* w_qkv  = (const float*)d_in[1];
    const float* w_o    = (const float*)d_in[2];
    const float* lscale = (const float*)d_in[3];
    const float* lls    = (const float*)d_in[4];
    float* out = (float*)d_out;

    float* att;
    __nv_bfloat16 *aexp, *bexp, *bexp2;
    cudaGetSymbolAddress((void**)&att, g_att);
    cudaGetSymbolAddress((void**)&aexp, g_aexp);
    cudaGetSymbolAddress((void**)&bexp, g_bexp);
    cudaGetSymbolAddress((void**)&bexp2, g_bexp2);

    const int M = BATCH * NSEQ;   // 4096
    cudaFuncSetAttribute(attn3_kernel, cudaFuncAttributeMaxDynamicSharedMemorySize, ATT_SMEM);

    // 1) theta/cos/sin + per-key bias (needed by GEMM1 epilogue + attention)
    prep_kernel<<<(NHEADS * NSEQ + 127) / 128, 128>>>(lscale, lls);

    // 2) bf16x3 conversions for QKV GEMM
    convA_kernel<<<(M * 128 + 255) / 256, 256>>>(x, aexp, M);
    convB_kernel<<<(3 * DMODEL * DMODEL + 255) / 256, 256>>>(w_qkv, bexp, 3 * DMODEL);

    // 3) QKV projection; epilogue rotates and emits split-bf16 Q'/K'/Vh/Vl
    mmagemm<0><<<dim3(3 * DMODEL / 128, M / 128), 256>>>(aexp, bexp, nullptr, 3 * DMODEL);

    // 4) tensor-core flash attention with per-key bias
    attn3_kernel<<<dim3(BATCH * NHEADS, NSEQ / 128), 256, ATT_SMEM>>>();

    // 5) output projection
    convA_kernel<<<(M * 128 + 255) / 256, 256>>>(att, aexp, M);
    convB_kernel<<<(DMODEL * DMODEL + 255) / 256, 256>>>(w_o, bexp2, DMODEL);
    mmagemm<1><<<dim3(DMODEL / 128, M / 128), 256>>>(aexp, bexp2, out, DMODEL);
}

// round 7
// speedup vs baseline: 6.9325x; 1.0316x over previous
#include <cuda_runtime.h>
#include <cuda_bf16.h>
#include <cstdint>
#include <math.h>

#define BATCH   2
#define NSEQ    2048
#define DMODEL  512
#define NHEADS  8
#define DH      64
#define KP      32
#define KEXP    1536
#define TAU_F   6.283185307179586f

// ---------------- scratch (static device memory; no allocations) ----------------
__device__ __nv_bfloat16 g_qe[(size_t)BATCH * NHEADS * NSEQ * 192];  // [qh|ql|qh]
__device__ __nv_bfloat16 g_ke[(size_t)BATCH * NHEADS * NSEQ * 192];  // [kh|kh|kl]
__device__ __nv_bfloat16 g_vh[(size_t)BATCH * NHEADS * NSEQ * DH];
__device__ __nv_bfloat16 g_vl[(size_t)BATCH * NHEADS * NSEQ * DH];
__device__ float g_cos[NHEADS * NSEQ * KP];
__device__ float g_sin[NHEADS * NSEQ * KP];
__device__ float g_bias[NHEADS * NSEQ];                             // lam*S_n/KP per head
__device__ float g_att[(size_t)BATCH * NSEQ * DMODEL];              // (b,n,h*dh)
__device__ __nv_bfloat16 g_aexp[(size_t)BATCH * NSEQ * KEXP];       // A' 4096x1536
__device__ __nv_bfloat16 g_bexp[(size_t)3 * DMODEL * KEXP];         // B' 1536x1536
__device__ __nv_bfloat16 g_bexp2[(size_t)DMODEL * KEXP];            // B2' 512x1536

__constant__ float c_zim[KP] = {
    14.134725142f, 21.022039639f, 25.01085758f,  30.424876126f,
    32.935061588f, 37.586178159f, 40.918719012f, 43.327073281f,
    48.005150881f, 49.773832478f, 52.970321478f, 56.446247697f,
    59.347044003f, 60.831778525f, 65.112544048f, 67.079810529f,
    69.546401711f, 72.067157674f, 75.704690699f, 77.144840069f,
    79.33737502f,  82.910380854f, 84.735492981f, 87.425274613f,
    88.809111208f, 92.491899271f, 94.651344041f, 95.870634228f,
    98.831194218f, 101.317851006f, 103.72553804f, 105.446623052f};

// ---------------- warp-MMA / async helpers (portable sm_80+ path) ----------------
__device__ __forceinline__ uint32_t smem_u32(const void* p) {
    uint32_t a;
    asm("{ .reg .u64 t; cvta.to.shared.u64 t, %1; cvt.u32.u64 %0, t; }" : "=r"(a) : "l"(p));
    return a;
}
__device__ __forceinline__ void ldsm4(uint32_t* r, uint32_t a) {
    asm volatile("ldmatrix.sync.aligned.m8n8.x4.shared.b16 {%0,%1,%2,%3}, [%4];"
                 : "=r"(r[0]), "=r"(r[1]), "=r"(r[2]), "=r"(r[3]) : "r"(a));
}
__device__ __forceinline__ void ldsm4t(uint32_t* r, uint32_t a) {
    asm volatile("ldmatrix.sync.aligned.m8n8.x4.trans.shared.b16 {%0,%1,%2,%3}, [%4];"
                 : "=r"(r[0]), "=r"(r[1]), "=r"(r[2]), "=r"(r[3]) : "r"(a));
}
__device__ __forceinline__ void mma16816(float* c, const uint32_t* a, uint32_t b0, uint32_t b1) {
    asm volatile("mma.sync.aligned.m16n8k16.row.col.f32.bf16.bf16.f32 "
                 "{%0,%1,%2,%3}, {%4,%5,%6,%7}, {%8,%9}, {%0,%1,%2,%3};"
                 : "+f"(c[0]), "+f"(c[1]), "+f"(c[2]), "+f"(c[3])
                 : "r"(a[0]), "r"(a[1]), "r"(a[2]), "r"(a[3]), "r"(b0), "r"(b1));
}
__device__ __forceinline__ void cpasync16(uint32_t dst, const void* src) {
    asm volatile("cp.async.cg.shared.global [%0], [%1], 16;" :: "r"(dst), "l"(src));
}
__device__ __forceinline__ void cpcommit() {
    asm volatile("cp.async.commit_group;");
}
template <int N>
__device__ __forceinline__ void cpwait() {
    asm volatile("cp.async.wait_group %0;" :: "n"(N));
}

// ---------------- bf16 mma GEMM, 4-stage cp.async pipeline ----------------
// C[M,Ntot] = A'[M,1536] @ B'[Ntot,1536]^T, 128x128 CTA tile, K-tiles of 32.
#define KT (KEXP / 32)
#define SWZ(r, bc) ((uint32_t)((r) * 64 + ((bc) ^ ((((r) >> 1) & 3) << 4))))
#define GSTAGES 4
#define GSTG_SZ 16384               // A(8KB) + B(8KB) per stage
#define GEMM_SMEM (GSTAGES * GSTG_SZ)

template <int EPI>
__global__ __launch_bounds__(256) void mmagemm(const __nv_bfloat16* __restrict__ A,
                                               const __nv_bfloat16* __restrict__ Bm,
                                               float* __restrict__ C, int Ntot) {
    extern __shared__ char gsm[];
    const uint32_t sbase = smem_u32(gsm);

    const int tid = threadIdx.x;
    const int lane = tid & 31;
    const int wid = tid >> 5;
    const int wm = (wid & 1) * 64;
    const int wn = (wid >> 1) * 32;
    const int row0 = blockIdx.y * 128;
    const int col0 = blockIdx.x * 128;

    // ldmatrix per-lane offsets
    const int lr = (lane & 7) + ((lane >> 3) & 1) * 8;
    const int kh = (lane >> 4) * 16;
    uint32_t aoff[4][2], boff[2][2];
#pragma unroll
    for (int mi = 0; mi < 4; mi++)
#pragma unroll
        for (int ks = 0; ks < 2; ks++) aoff[mi][ks] = SWZ(wm + mi * 16 + lr, ks * 32 + kh);
#pragma unroll
    for (int g = 0; g < 2; g++)
#pragma unroll
        for (int ks = 0; ks < 2; ks++) boff[g][ks] = SWZ(wn + g * 16 + lr, ks * 32 + kh);

    // cp.async mapping: thread covers rows r_ld0 and r_ld0+64, 16B each
    const int r_ld0 = tid >> 2, cu_ld = tid & 3;
    const int r_ld1 = r_ld0 + 64;
    const uint32_t so0 = SWZ(r_ld0, cu_ld * 16);
    const uint32_t so1 = SWZ(r_ld1, cu_ld * 16);
    const __nv_bfloat16* a0p = &A[(size_t)(row0 + r_ld0) * KEXP + cu_ld * 8];
    const __nv_bfloat16* a1p = &A[(size_t)(row0 + r_ld1) * KEXP + cu_ld * 8];
    const __nv_bfloat16* b0p = &Bm[(size_t)(col0 + r_ld0) * KEXP + cu_ld * 8];
    const __nv_bfloat16* b1p = &Bm[(size_t)(col0 + r_ld1) * KEXP + cu_ld * 8];

    auto load_tile = [&](int t) {
        const uint32_t st = sbase + (uint32_t)((t % GSTAGES) * GSTG_SZ);
        const int k0 = t * 32;
        cpasync16(st + so0, a0p + k0);
        cpasync16(st + so1, a1p + k0);
        cpasync16(st + 8192 + so0, b0p + k0);
        cpasync16(st + 8192 + so1, b1p + k0);
        cpcommit();
    };
    load_tile(0);
    load_tile(1);
    load_tile(2);

    float acc[4][4][4];
#pragma unroll
    for (int mi = 0; mi < 4; mi++)
#pragma unroll
        for (int ni = 0; ni < 4; ni++)
#pragma unroll
            for (int q = 0; q < 4; q++) acc[mi][ni][q] = 0.0f;

    for (int t = 0; t < KT; t++) {
        cpwait<2>();
        __syncthreads();
        const uint32_t baseA = sbase + (uint32_t)((t % GSTAGES) * GSTG_SZ);
        const uint32_t baseB = baseA + 8192;
#pragma unroll
        for (int ks = 0; ks < 2; ks++) {
            uint32_t af[4][4], bf[2][4];
#pragma unroll
            for (int mi = 0; mi < 4; mi++) ldsm4(af[mi], baseA + aoff[mi][ks]);
#pragma unroll
            for (int g = 0; g < 2; g++) ldsm4(bf[g], baseB + boff[g][ks]);
#pragma unroll
            for (int mi = 0; mi < 4; mi++)
#pragma unroll
                for (int ni = 0; ni < 4; ni++)
                    mma16816(acc[mi][ni], af[mi], bf[ni >> 1][ni & 1], bf[ni >> 1][(ni & 1) + 2]);
        }
        if (t + 3 < KT) load_tile(t + 3);
        else cpcommit();   // empty group keeps wait_group accounting exact
    }

    // epilogue: fragment (mi,ni): c0,c1 at (m, n..n+1), c2,c3 at (m+8, n..n+1)
#pragma unroll
    for (int mi = 0; mi < 4; mi++) {
#pragma unroll
        for (int ni = 0; ni < 4; ni++) {
            int m0 = row0 + wm + mi * 16 + (lane >> 2);
            int n = col0 + wn + ni * 8 + (lane & 3) * 2;
#pragma unroll
            for (int half = 0; half < 2; half++) {
                int m = m0 + half * 8;
                float v0 = acc[mi][ni][half * 2 + 0];
                float v1 = acc[mi][ni][half * 2 + 1];
                if (EPI == 1) {
                    *reinterpret_cast<float2*>(&C[(size_t)m * Ntot + n]) = make_float2(v0, v1);
                } else {
                    const int bb = m >> 11, nn = m & 2047;
                    const int sect = n >> 9;
                    const int h = (n >> 6) & 7;
                    const int d = n & 63;
                    if (sect == 2) {
                        __nv_bfloat162 hi = __float22bfloat162_rn(make_float2(v0, v1));
                        __nv_bfloat162 lo = __float22bfloat162_rn(
                            make_float2(v0 - __low2float(hi), v1 - __high2float(hi)));
                        size_t vb = ((size_t)((bb * NHEADS + h) * NSEQ) + nn) * DH + d;
                        *reinterpret_cast<__nv_bfloat162*>(&g_vh[vb]) = hi;
                        *reinterpret_cast<__nv_bfloat162*>(&g_vl[vb]) = lo;
                    } else {
                        int ci = (h * NSEQ + nn) * KP + (d >> 1);
                        float c0 = g_cos[ci], s0 = g_sin[ci];
                        float o0 = v0 * c0 - v1 * s0;
                        float o1 = v0 * s0 + v1 * c0;
                        __nv_bfloat162 hi = __float22bfloat162_rn(make_float2(o0, o1));
                        __nv_bfloat162 lo = __float22bfloat162_rn(
                            make_float2(o0 - __low2float(hi), o1 - __high2float(hi)));
                        size_t qb = ((size_t)((bb * NHEADS + h) * NSEQ) + nn) * 192 + d;
                        if (sect == 0) {   // Q: [hi | lo | hi]
                            *reinterpret_cast<__nv_bfloat162*>(&g_qe[qb]) = hi;
                            *reinterpret_cast<__nv_bfloat162*>(&g_qe[qb + 64]) = lo;
                            *reinterpret_cast<__nv_bfloat162*>(&g_qe[qb + 128]) = hi;
                        } else {           // K: [hi | hi | lo]
                            *reinterpret_cast<__nv_bfloat162*>(&g_ke[qb]) = hi;
                            *reinterpret_cast<__nv_bfloat162*>(&g_ke[qb + 64]) = hi;
                            *reinterpret_cast<__nv_bfloat162*>(&g_ke[qb + 128]) = lo;
                        }
                    }
                }
            }
        }
    }
}

// ---------------- bf16x3 split conversions ----------------
__global__ void convA_kernel(const float* __restrict__ src, __nv_bfloat16* __restrict__ dst, int M) {
    int i = blockIdx.x * blockDim.x + threadIdx.x;
    if (i >= M * 128) return;
    int row = i >> 7, c4 = (i & 127) * 4;
    float4 v = *reinterpret_cast<const float4*>(&src[(size_t)row * DMODEL + c4]);
    __nv_bfloat16 h0 = __float2bfloat16(v.x), h1 = __float2bfloat16(v.y);
    __nv_bfloat16 h2 = __float2bfloat16(v.z), h3 = __float2bfloat16(v.w);
    __nv_bfloat16 l0 = __float2bfloat16(v.x - __bfloat162float(h0));
    __nv_bfloat16 l1 = __float2bfloat16(v.y - __bfloat162float(h1));
    __nv_bfloat16 l2 = __float2bfloat16(v.z - __bfloat162float(h2));
    __nv_bfloat16 l3 = __float2bfloat16(v.w - __bfloat162float(h3));
    size_t base = (size_t)row * KEXP + c4;
    __nv_bfloat162* d0 = reinterpret_cast<__nv_bfloat162*>(&dst[base]);
    __nv_bfloat162* d1 = reinterpret_cast<__nv_bfloat162*>(&dst[base + 512]);
    __nv_bfloat162* d2 = reinterpret_cast<__nv_bfloat162*>(&dst[base + 1024]);
    d0[0] = __nv_bfloat162(h0, h1); d0[1] = __nv_bfloat162(h2, h3);
    d1[0] = __nv_bfloat162(l0, l1); d1[1] = __nv_bfloat162(l2, l3);
    d2[0] = __nv_bfloat162(h0, h1); d2[1] = __nv_bfloat162(h2, h3);
}

__global__ void convB_kernel(const float* __restrict__ w, __nv_bfloat16* __restrict__ dst, int N) {
    int i = blockIdx.x * blockDim.x + threadIdx.x;
    if (i >= N * DMODEL) return;
    int k = i & 511, n = i >> 9;
    float v = w[(size_t)k * N + n];
    __nv_bfloat16 hi = __float2bfloat16(v);
    __nv_bfloat16 lo = __float2bfloat16(v - __bfloat162float(hi));
    size_t base = (size_t)n * KEXP + k;
    dst[base] = hi;
    dst[base + 512] = hi;
    dst[base + 1024] = lo;
}

// ---------------- theta / cos / sin / per-key bias ----------------
__global__ void prep_kernel(const float* __restrict__ log_scale,
                            const float* __restrict__ log_lambda_sigma) {
    int idx = blockIdx.x * blockDim.x + threadIdx.x;
    if (idx >= NHEADS * NSEQ) return;
    int h = idx / NSEQ;
    int n = idx % NSEQ;
    float sc = expf(log_scale[h]);
    float lam = expf(log_lambda_sigma[h]);
    float tau = log1pf((float)n);
    float ssum = 0.0f;
#pragma unroll
    for (int p = 0; p < KP; p++) {
        float g = c_zim[p] / c_zim[0];
        float th = tau * g * sc;
        g_cos[idx * KP + p] = cosf(th);
        g_sin[idx * KP + p] = sinf(th);
        ssum += floorf(th / TAU_F);
    }
    g_bias[idx] = lam * ssum * (1.0f / KP);
}

// ---------------- tensor-core flash attention (bf16 split-compensated) ----------------
#define QOFF   0
#define QSZ    (128 * 400)
#define STSZ   (64 * 400 + 2 * 64 * 144 + 256)
#define KOFF(s)  (QSZ + (s) * STSZ)
#define VHOFF(s) (KOFF(s) + 64 * 400)
#define VLOFF(s) (VHOFF(s) + 64 * 144)
#define BOFF(s)  (VLOFF(s) + 64 * 144)
#define ATT_SMEM (QSZ + 2 * STSZ)

__global__ __launch_bounds__(256) void attn3_kernel() {
    extern __shared__ char smc[];
    const uint32_t smb = smem_u32(smc);
    const int tid = threadIdx.x;
    const int lane = tid & 31;
    const int wid = tid >> 5;
    const int bh = blockIdx.x;
    const int h = bh & (NHEADS - 1);
    const int b = bh >> 3;
    const int qbase = (15 - (int)blockIdx.y) << 7;
    const int ntiles = (qbase >> 6) + 2;

    const __nv_bfloat16* qe = g_qe + (size_t)bh * NSEQ * 192;
    const __nv_bfloat16* ke = g_ke + (size_t)bh * NSEQ * 192;
    const __nv_bfloat16* vh = g_vh + (size_t)bh * NSEQ * DH;
    const __nv_bfloat16* vl = g_vl + (size_t)bh * NSEQ * DH;
    const float* bp = g_bias + h * NSEQ;

    for (int i = tid; i < 3072; i += 256) {
        int r = i / 24, c = i % 24;
        cpasync16(smb + QOFF + r * 400 + c * 16, qe + (size_t)(qbase + r) * 192 + c * 8);
    }
    auto load_tile = [&](int t, int st) {
        int jg = t << 6;
#pragma unroll
        for (int q = 0; q < 6; q++) {
            int i = q * 256 + tid, r = i / 24, c = i % 24;
            cpasync16(smb + KOFF(st) + r * 400 + c * 16, ke + (size_t)(jg + r) * 192 + c * 8);
        }
#pragma unroll
        for (int q = 0; q < 2; q++) {
            int i = q * 256 + tid, r = i >> 3, c = i & 7;
            cpasync16(smb + VHOFF(st) + r * 144 + c * 16, vh + (size_t)(jg + r) * DH + c * 8);
            cpasync16(smb + VLOFF(st) + r * 144 + c * 16, vl + (size_t)(jg + r) * DH + c * 8);
        }
        if (tid < 16) cpasync16(smb + BOFF(st) + tid * 16, bp + jg + tid * 4);
    };
    load_tile(0, 0);
    cpcommit();
    load_tile(1, 1);
    cpcommit();

    const uint32_t qaddr = smb + QOFF + (wid * 16 + (lane & 15)) * 400 + (lane >> 4) * 16;
    const uint32_t klocal = (uint32_t)((lane & 15) * 400 + (lane >> 4) * 16);
    const uint32_t vlocal = (uint32_t)((lane & 15) * 144 + (lane >> 4) * 16);

    float o[8][4];
#pragma unroll
    for (int i = 0; i < 8; i++)
#pragma unroll
        for (int q = 0; q < 4; q++) o[i][q] = 0.0f;
    float m0 = -INFINITY, m1 = -INFINITY, l0 = 0.0f, l1 = 0.0f;
    const int qm0 = qbase + wid * 16 + (lane >> 2);
    const int qm1 = qm0 + 8;

    for (int t = 0; t < ntiles; t++) {
        if (t < ntiles - 1) cpwait<1>(); else cpwait<0>();
        __syncthreads();
        const int st = t & 1;
        const int jg = t << 6;

        float s[8][4];
#pragma unroll
        for (int i = 0; i < 8; i++)
#pragma unroll
            for (int q = 0; q < 4; q++) s[i][q] = 0.0f;
        const uint32_t kb = smb + KOFF(st);
#pragma unroll
        for (int ks = 0; ks < 12; ks++) {
            uint32_t a[4];
            ldsm4(a, qaddr + ks * 32);
            uint32_t bf[4][4];
#pragma unroll
            for (int ng = 0; ng < 4; ng++) ldsm4(bf[ng], kb + klocal + ng * 6400 + ks * 32);
#pragma unroll
            for (int nf = 0; nf < 8; nf++)
                mma16816(s[nf], a, bf[nf >> 1][nf & 1], bf[nf >> 1][(nf & 1) + 2]);
        }

        const bool masked = (t >= ntiles - 2);
#pragma unroll
        for (int nf = 0; nf < 8; nf++) {
            int col = jg + nf * 8 + ((lane & 3) << 1);
            float2 bj = *reinterpret_cast<const float2*>(smc + BOFF(st) + (nf * 8 + ((lane & 3) << 1)) * 4);
            s[nf][0] = s[nf][0] * 0.125f + bj.x;
            s[nf][1] = s[nf][1] * 0.125f + bj.y;
            s[nf][2] = s[nf][2] * 0.125f + bj.x;
            s[nf][3] = s[nf][3] * 0.125f + bj.y;
            if (masked) {
                if (col > qm0)     s[nf][0] = -INFINITY;
                if (col + 1 > qm0) s[nf][1] = -INFINITY;
                if (col > qm1)     s[nf][2] = -INFINITY;
                if (col + 1 > qm1) s[nf][3] = -INFINITY;
            }
        }

        float mx0 = -INFINITY, mx1 = -INFINITY;
#pragma unroll
        for (int nf = 0; nf < 8; nf++) {
            mx0 = fmaxf(mx0, fmaxf(s[nf][0], s[nf][1]));
            mx1 = fmaxf(mx1, fmaxf(s[nf][2], s[nf][3]));
        }
        mx0 = fmaxf(mx0, __shfl_xor_sync(0xffffffffu, mx0, 1));
        mx0 = fmaxf(mx0, __shfl_xor_sync(0xffffffffu, mx0, 2));
        mx1 = fmaxf(mx1, __shfl_xor_sync(0xffffffffu, mx1, 1));
        mx1 = fmaxf(mx1, __shfl_xor_sync(0xffffffffu, mx1, 2));
        float mn0 = fmaxf(m0, mx0), mn1 = fmaxf(m1, mx1);
        float corr0 = __expf(m0 - mn0), corr1 = __expf(m1 - mn1);
        m0 = mn0; m1 = mn1;
        float ps0 = 0.0f, ps1 = 0.0f;
#pragma unroll
        for (int nf = 0; nf < 8; nf++) {
            s[nf][0] = __expf(s[nf][0] - mn0);
            s[nf][1] = __expf(s[nf][1] - mn0);
            s[nf][2] = __expf(s[nf][2] - mn1);
            s[nf][3] = __expf(s[nf][3] - mn1);
            ps0 += s[nf][0] + s[nf][1];
            ps1 += s[nf][2] + s[nf][3];
        }
        ps0 += __shfl_xor_sync(0xffffffffu, ps0, 1);
        ps0 += __shfl_xor_sync(0xffffffffu, ps0, 2);
        ps1 += __shfl_xor_sync(0xffffffffu, ps1, 1);
        ps1 += __shfl_xor_sync(0xffffffffu, ps1, 2);
        l0 = l0 * corr0 + ps0;
        l1 = l1 * corr1 + ps1;
#pragma unroll
        for (int nf = 0; nf < 8; nf++) {
            o[nf][0] *= corr0; o[nf][1] *= corr0;
            o[nf][2] *= corr1; o[nf][3] *= corr1;
        }

        const uint32_t vhb = smb + VHOFF(st);
        const uint32_t vlb = smb + VLOFF(st);
#pragma unroll
        for (int ks2 = 0; ks2 < 4; ks2++) {
            const int f0 = 2 * ks2, f1 = 2 * ks2 + 1;
            __nv_bfloat162 h0 = __float22bfloat162_rn(make_float2(s[f0][0], s[f0][1]));
            __nv_bfloat162 h1 = __float22bfloat162_rn(make_float2(s[f0][2], s[f0][3]));
            __nv_bfloat162 h2 = __float22bfloat162_rn(make_float2(s[f1][0], s[f1][1]));
            __nv_bfloat162 h3 = __float22bfloat162_rn(make_float2(s[f1][2], s[f1][3]));
            __nv_bfloat162 e0 = __float22bfloat162_rn(
                make_float2(s[f0][0] - __low2float(h0), s[f0][1] - __high2float(h0)));
            __nv_bfloat162 e1 = __float22bfloat162_rn(
                make_float2(s[f0][2] - __low2float(h1), s[f0][3] - __high2float(h1)));
            __nv_bfloat162 e2 = __float22bfloat162_rn(
                make_float2(s[f1][0] - __low2float(h2), s[f1][1] - __high2float(h2)));
            __nv_bfloat162 e3 = __float22bfloat162_rn(
                make_float2(s[f1][2] - __low2float(h3), s[f1][3] - __high2float(h3)));
            uint32_t ah[4] = {*(uint32_t*)&h0, *(uint32_t*)&h1, *(uint32_t*)&h2, *(uint32_t*)&h3};
            uint32_t al[4] = {*(uint32_t*)&e0, *(uint32_t*)&e1, *(uint32_t*)&e2, *(uint32_t*)&e3};
#pragma unroll
            for (int dseg = 0; dseg < 4; dseg++) {
                uint32_t bhf[4], blf[4];
                ldsm4t(bhf, vhb + ks2 * 2304 + vlocal + dseg * 32);
                ldsm4t(blf, vlb + ks2 * 2304 + vlocal + dseg * 32);
                mma16816(o[2 * dseg],     ah, bhf[0], bhf[1]);
                mma16816(o[2 * dseg + 1], ah, bhf[2], bhf[3]);
                mma16816(o[2 * dseg],     al, bhf[0], bhf[1]);
                mma16816(o[2 * dseg + 1], al, bhf[2], bhf[3]);
                mma16816(o[2 * dseg],     ah, blf[0], blf[1]);
                mma16816(o[2 * dseg + 1], ah, blf[2], blf[3]);
            }
        }

        __syncthreads();
        if (t + 2 < ntiles) { load_tile(t + 2, st); cpcommit(); }
    }

    const float inv0 = 1.0f / l0, inv1 = 1.0f / l1;
#pragma unroll
    for (int nf = 0; nf < 8; nf++) {
        int col = h * DH + nf * 8 + ((lane & 3) << 1);
        *reinterpret_cast<float2*>(&g_att[(size_t)(b * NSEQ + qm0) * DMODEL + col]) =
            make_float2(o[nf][0] * inv0, o[nf][1] * inv0);
        *reinterpret_cast<float2*>(&g_att[(size_t)(b * NSEQ + qm1) * DMODEL + col]) =
            make_float2(o[nf][2] * inv1, o[nf][3] * inv1);
    }
}

// ---------------- launch ----------------
extern "C" void kernel_launch(void* const* d_in, const int* in_sizes, int n_in,
                              void* d_out, int out_size) {
    const float* x      = (const float*)d_in[0];
    const float* w_qkv  = (const float*)d_in[1];
    const float* w_o    = (const float*)d_in[2];
    const float* lscale = (const float*)d_in[3];
    const float* lls    = (const float*)d_in[4];
    float* out = (float*)d_out;

    float* att;
    __nv_bfloat16 *aexp, *bexp, *bexp2;
    cudaGetSymbolAddress((void**)&att, g_att);
    cudaGetSymbolAddress((void**)&aexp, g_aexp);
    cudaGetSymbolAddress((void**)&bexp, g_bexp);
    cudaGetSymbolAddress((void**)&bexp2, g_bexp2);

    const int M = BATCH * NSEQ;   // 4096
    cudaFuncSetAttribute(attn3_kernel, cudaFuncAttributeMaxDynamicSharedMemorySize, ATT_SMEM);
    cudaFuncSetAttribute(mmagemm<0>, cudaFuncAttributeMaxDynamicSharedMemorySize, GEMM_SMEM);
    cudaFuncSetAttribute(mmagemm<1>, cudaFuncAttributeMaxDynamicSharedMemorySize, GEMM_SMEM);

    // 1) theta/cos/sin + per-key bias (needed by GEMM1 epilogue + attention)
    prep_kernel<<<(NHEADS * NSEQ + 127) / 128, 128>>>(lscale, lls);

    // 2) bf16x3 conversions for QKV GEMM
    convA_kernel<<<(M * 128 + 255) / 256, 256>>>(x, aexp, M);
    convB_kernel<<<(3 * DMODEL * DMODEL + 255) / 256, 256>>>(w_qkv, bexp, 3 * DMODEL);

    // 3) QKV projection; epilogue rotates and emits split-bf16 Q'/K'/Vh/Vl
    mmagemm<0><<<dim3(3 * DMODEL / 128, M / 128), 256, GEMM_SMEM>>>(aexp, bexp, nullptr, 3 * DMODEL);

    // 4) tensor-core flash attention with per-key bias
    attn3_kernel<<<dim3(BATCH * NHEADS, NSEQ / 128), 256, ATT_SMEM>>>();

    // 5) output projection
    convA_kernel<<<(M * 128 + 255) / 256, 256>>>(att, aexp, M);
    convB_kernel<<<(DMODEL * DMODEL + 255) / 256, 256>>>(w_o, bexp2, DMODEL);
    mmagemm<1><<<dim3(DMODEL / 128, M / 128), 256, GEMM_SMEM>>>(aexp, bexp2, out, DMODEL);
}